// round 1
// baseline (speedup 1.0000x reference)
#include <cuda_runtime.h>
#include <math.h>

#define T_STEPS 128
#define N_ENV   512
#define IN_D    512
#define HID     512
#define G3      (3 * HID)      // 1536
#define LN_EPS  1e-5f

// Scratch: GI for all timesteps (T*N, 3H), GH for one step (N, 3H).
__device__ float g_gi[(size_t)T_STEPS * N_ENV * G3];   // ~402 MB
__device__ float g_gh[(size_t)N_ENV * G3];             // 3 MB

// ---------------------------------------------------------------------------
// Generic C[M,Nc] = (rowmask ? diag(mask) : I) * A[M,K] @ B[Nc,K]^T + bias[Nc]
// 64x64 tile, BK=16, 256 threads, 4x4 microtile, float4 everywhere.
// ---------------------------------------------------------------------------
#define BM 64
#define BN 64
#define BK 16
#define PAD 4

__global__ void __launch_bounds__(256)
gemm_tn(const float* __restrict__ A, const float* __restrict__ B,
        const float* __restrict__ bias, const float* __restrict__ rowmask,
        float* __restrict__ C, int M, int Nc, int K)
{
    __shared__ float As[BK][BM + PAD];
    __shared__ float Bs[BK][BN + PAD];

    const int bm  = blockIdx.y * BM;
    const int bn  = blockIdx.x * BN;
    const int tid = threadIdx.x;
    const int ar  = tid >> 2;          // 0..63 : tile row loaded by this thread
    const int ac  = (tid & 3) << 2;    // 0,4,8,12 : k offset (float4)
    const int ty  = tid >> 4;          // 0..15
    const int tx  = tid & 15;          // 0..15

    float acc[4][4] = {};
    float msk = 1.0f;
    if (rowmask) msk = rowmask[bm + ar];

    const float* Arow = A + (size_t)(bm + ar) * K;
    const float* Brow = B + (size_t)(bn + ar) * K;

    for (int k0 = 0; k0 < K; k0 += BK) {
        float4 av = *(const float4*)(Arow + k0 + ac);
        av.x *= msk; av.y *= msk; av.z *= msk; av.w *= msk;
        As[ac + 0][ar] = av.x; As[ac + 1][ar] = av.y;
        As[ac + 2][ar] = av.z; As[ac + 3][ar] = av.w;

        float4 bv = *(const float4*)(Brow + k0 + ac);
        Bs[ac + 0][ar] = bv.x; Bs[ac + 1][ar] = bv.y;
        Bs[ac + 2][ar] = bv.z; Bs[ac + 3][ar] = bv.w;

        __syncthreads();

#pragma unroll
        for (int k = 0; k < BK; ++k) {
            float4 a = *(const float4*)&As[k][ty << 2];
            float4 b = *(const float4*)&Bs[k][tx << 2];
            acc[0][0] += a.x * b.x; acc[0][1] += a.x * b.y;
            acc[0][2] += a.x * b.z; acc[0][3] += a.x * b.w;
            acc[1][0] += a.y * b.x; acc[1][1] += a.y * b.y;
            acc[1][2] += a.y * b.z; acc[1][3] += a.y * b.w;
            acc[2][0] += a.z * b.x; acc[2][1] += a.z * b.y;
            acc[2][2] += a.z * b.z; acc[2][3] += a.z * b.w;
            acc[3][0] += a.w * b.x; acc[3][1] += a.w * b.y;
            acc[3][2] += a.w * b.z; acc[3][3] += a.w * b.w;
        }
        __syncthreads();
    }

    float4 bb = *(const float4*)(bias + bn + (tx << 2));
#pragma unroll
    for (int i = 0; i < 4; ++i) {
        float4 o;
        o.x = acc[i][0] + bb.x; o.y = acc[i][1] + bb.y;
        o.z = acc[i][2] + bb.z; o.w = acc[i][3] + bb.w;
        *(float4*)(C + (size_t)(bm + (ty << 2) + i) * Nc + bn + (tx << 2)) = o;
    }
}

// ---------------------------------------------------------------------------
// Fused GRU gate update for one timestep.
//   h      = h_prev * m
//   r      = sigmoid(gi_r + gh_r)
//   z      = sigmoid(gi_z + gh_z)
//   n      = tanh(gi_n + r * gh_n)
//   h_new  = (1 - z) * n + z * h
// ---------------------------------------------------------------------------
__global__ void __launch_bounds__(256)
gru_gate(const float* __restrict__ gi, const float* __restrict__ gh,
         const float* __restrict__ hprev, const float* __restrict__ mask,
         float* __restrict__ hout)
{
    int idx = blockIdx.x * 256 + threadIdx.x;      // over N_ENV * HID
    int i = idx >> 9;                              // env (HID = 512)
    int c = idx & (HID - 1);

    float m  = mask[i];
    float h  = hprev[idx] * m;

    size_t base = (size_t)i * G3 + c;
    float ir = gi[base];
    float iz = gi[base + HID];
    float in_ = gi[base + 2 * HID];
    float hr = gh[base];
    float hz = gh[base + HID];
    float hn = gh[base + 2 * HID];

    float r = 1.0f / (1.0f + __expf(-(ir + hr)));
    float z = 1.0f / (1.0f + __expf(-(iz + hz)));
    float n = tanhf(in_ + r * hn);
    hout[idx] = (1.0f - z) * n + z * h;
}

// ---------------------------------------------------------------------------
// Copy last hidden state (raw, pre-LN) to the tail of d_out.
// ---------------------------------------------------------------------------
__global__ void __launch_bounds__(256)
copy_hlast(const float* __restrict__ src, float* __restrict__ dst)
{
    int idx = blockIdx.x * 256 + threadIdx.x;
    ((float4*)dst)[idx] = ((const float4*)src)[idx];
}

// ---------------------------------------------------------------------------
// In-place row LayerNorm over (T*N, H). One 128-thread block per row.
// ---------------------------------------------------------------------------
__global__ void __launch_bounds__(128)
layernorm_rows(float* __restrict__ data, const float* __restrict__ w,
               const float* __restrict__ b)
{
    __shared__ float ss[4], sqs[4];
    float* p = data + (size_t)blockIdx.x * HID;
    int t = threadIdx.x;

    float4 v = ((const float4*)p)[t];
    float s  = v.x + v.y + v.z + v.w;
    float sq = v.x * v.x + v.y * v.y + v.z * v.z + v.w * v.w;

#pragma unroll
    for (int o = 16; o > 0; o >>= 1) {
        s  += __shfl_xor_sync(0xffffffffu, s,  o);
        sq += __shfl_xor_sync(0xffffffffu, sq, o);
    }
    int warp = t >> 5;
    if ((t & 31) == 0) { ss[warp] = s; sqs[warp] = sq; }
    __syncthreads();
    s  = ss[0]  + ss[1]  + ss[2]  + ss[3];
    sq = sqs[0] + sqs[1] + sqs[2] + sqs[3];

    float mu  = s * (1.0f / HID);
    float var = sq * (1.0f / HID) - mu * mu;
    float inv = rsqrtf(var + LN_EPS);

    float4 wv = ((const float4*)w)[t];
    float4 bv = ((const float4*)b)[t];
    float4 o;
    o.x = (v.x - mu) * inv * wv.x + bv.x;
    o.y = (v.y - mu) * inv * wv.y + bv.y;
    o.z = (v.z - mu) * inv * wv.z + bv.z;
    o.w = (v.w - mu) * inv * wv.w + bv.w;
    ((float4*)p)[t] = o;
}

// ---------------------------------------------------------------------------
extern "C" void kernel_launch(void* const* d_in, const int* in_sizes, int n_in,
                              void* d_out, int out_size)
{
    const float* x     = (const float*)d_in[0];   // (T*N, IN)
    const float* hxs   = (const float*)d_in[1];   // (N, H)
    const float* masks = (const float*)d_in[2];   // (T*N, 1)
    const float* W_ih  = (const float*)d_in[3];   // (3H, IN)
    const float* W_hh  = (const float*)d_in[4];   // (3H, H)
    const float* b_ih  = (const float*)d_in[5];   // (3H,)
    const float* b_hh  = (const float*)d_in[6];   // (3H,)
    const float* ln_w  = (const float*)d_in[7];   // (H,)
    const float* ln_b  = (const float*)d_in[8];   // (H,)
    float* out = (float*)d_out;                   // (T*N*H) normed + (N*H) h_last

    float *gi, *gh;
    cudaGetSymbolAddress((void**)&gi, g_gi);
    cudaGetSymbolAddress((void**)&gh, g_gh);

    // 1) GI = x @ W_ih^T + b_ih for all T*N rows at once.
    {
        dim3 grid(G3 / BN, (T_STEPS * N_ENV) / BM);
        gemm_tn<<<grid, 256>>>(x, W_ih, b_ih, nullptr, gi,
                               T_STEPS * N_ENV, G3, IN_D);
    }

    // 2) Recurrent scan: per step, gh GEMM (with row mask on h) + fused gates.
    dim3 ggrid(G3 / BN, N_ENV / BM);   // 24 x 8 = 192 blocks
    const int gate_blocks = (N_ENV * HID) / 256;
    for (int t = 0; t < T_STEPS; ++t) {
        const float* hprev = (t == 0) ? hxs : (out + (size_t)(t - 1) * N_ENV * HID);
        const float* mt    = masks + (size_t)t * N_ENV;
        gemm_tn<<<ggrid, 256>>>(hprev, W_hh, b_hh, mt, gh, N_ENV, G3, HID);
        gru_gate<<<gate_blocks, 256>>>(gi + (size_t)t * N_ENV * G3, gh,
                                       hprev, mt,
                                       out + (size_t)t * N_ENV * HID);
    }

    // 3) h_last (raw) to tail, before LN rewrites the rows.
    copy_hlast<<<(N_ENV * HID / 4) / 256, 256>>>(
        out + (size_t)(T_STEPS - 1) * N_ENV * HID,
        out + (size_t)T_STEPS * N_ENV * HID);

    // 4) In-place LayerNorm over all T*N rows.
    layernorm_rows<<<T_STEPS * N_ENV, 128>>>(out, ln_w, ln_b);
}

// round 3
// speedup vs baseline: 1.6149x; 1.6149x over previous
#include <cuda_runtime.h>
#include <cuda_bf16.h>
#include <cstdint>
#include <math.h>

#define T_STEPS 128
#define N_ENV   512
#define IN_D    512
#define HID     512
#define G3      (3 * HID)      // 1536
#define LN_EPS  1e-5f

// Scratch: GI for all timesteps (T*N, 3H), GH for one step (N, 3H).
__device__ float g_gi[(size_t)T_STEPS * N_ENV * G3];   // ~402 MB
__device__ float g_gh[(size_t)N_ENV * G3];             // 3 MB

// ===========================================================================
// Split-bf16 tensor-core GEMM:
//   C[M,Nc] = diag(rowmask) * A[M,K] @ B[Nc,K]^T + bias
// a = a_hi + a_lo (both bf16 RN); C ~= Ah*Bh + Al*Bh + Ah*Bl, fp32 accum.
// CTA tile 64x64, 4 warps of 32x32, BK=32, ldmatrix.x4, smem stride 40 bf16.
// ===========================================================================
#define BM   64
#define BN   64
#define BK   32
#define SSTR 40

__device__ __forceinline__ void ldsm_x4(uint32_t& r0, uint32_t& r1,
                                        uint32_t& r2, uint32_t& r3,
                                        uint32_t addr)
{
    asm volatile("ldmatrix.sync.aligned.m8n8.x4.shared.b16 {%0,%1,%2,%3}, [%4];\n"
                 : "=r"(r0), "=r"(r1), "=r"(r2), "=r"(r3) : "r"(addr));
}

__device__ __forceinline__ void mma_bf16(float* c, uint32_t a0, uint32_t a1,
                                         uint32_t a2, uint32_t a3,
                                         uint32_t b0, uint32_t b1)
{
    asm volatile("mma.sync.aligned.m16n8k16.row.col.f32.bf16.bf16.f32 "
                 "{%0,%1,%2,%3},{%4,%5,%6,%7},{%8,%9},{%0,%1,%2,%3};\n"
                 : "+f"(c[0]), "+f"(c[1]), "+f"(c[2]), "+f"(c[3])
                 : "r"(a0), "r"(a1), "r"(a2), "r"(a3), "r"(b0), "r"(b1));
}

__global__ void __launch_bounds__(128)
gemm_split_bf16(const float* __restrict__ A, const float* __restrict__ B,
                const float* __restrict__ bias, const float* __restrict__ rowmask,
                float* __restrict__ C, int M, int Nc, int K)
{
    __shared__ __nv_bfloat16 sA_hi[BM * SSTR];
    __shared__ __nv_bfloat16 sA_lo[BM * SSTR];
    __shared__ __nv_bfloat16 sB_hi[BN * SSTR];
    __shared__ __nv_bfloat16 sB_lo[BN * SSTR];

    const int tid  = threadIdx.x;
    const int w    = tid >> 5;
    const int lane = tid & 31;
    const int bm   = blockIdx.y * BM;
    const int bn   = blockIdx.x * BN;
    const int wm   = (w & 1) * 32;
    const int wn   = (w >> 1) * 32;

    float acc[2][4][4];
#pragma unroll
    for (int i = 0; i < 2; ++i)
#pragma unroll
        for (int j = 0; j < 4; ++j)
#pragma unroll
            for (int k = 0; k < 4; ++k) acc[i][j][k] = 0.0f;

    float mk[4];
#pragma unroll
    for (int i = 0; i < 4; ++i) {
        int row = (tid + i * 128) >> 3;
        mk[i] = rowmask ? rowmask[bm + row] : 1.0f;
    }

    const float* Ag = A + (size_t)bm * K;
    const float* Bg = B + (size_t)bn * K;

    const uint32_t sAhi = (uint32_t)__cvta_generic_to_shared(sA_hi);
    const uint32_t sAlo = (uint32_t)__cvta_generic_to_shared(sA_lo);
    const uint32_t sBhi = (uint32_t)__cvta_generic_to_shared(sB_hi);
    const uint32_t sBlo = (uint32_t)__cvta_generic_to_shared(sB_lo);

    const int a_row = wm + (lane & 7) + ((lane >> 3) & 1) * 8;
    const int a_k   = (lane >> 4) << 3;
    const int b_row = wn + (lane & 7) + ((lane >> 4) << 3);
    const int b_k   = ((lane >> 3) & 1) << 3;

    for (int k0 = 0; k0 < K; k0 += BK) {
#pragma unroll
        for (int i = 0; i < 4; ++i) {
            int idx = tid + i * 128;
            int row = idx >> 3;
            int c4  = (idx & 7) << 2;

            float4 v = *(const float4*)(Ag + (size_t)row * K + k0 + c4);
            v.x *= mk[i]; v.y *= mk[i]; v.z *= mk[i]; v.w *= mk[i];
            __nv_bfloat16 h0 = __float2bfloat16(v.x);
            __nv_bfloat16 h1 = __float2bfloat16(v.y);
            __nv_bfloat16 h2 = __float2bfloat16(v.z);
            __nv_bfloat16 h3 = __float2bfloat16(v.w);
            __nv_bfloat16 l0 = __float2bfloat16(v.x - __bfloat162float(h0));
            __nv_bfloat16 l1 = __float2bfloat16(v.y - __bfloat162float(h1));
            __nv_bfloat16 l2 = __float2bfloat16(v.z - __bfloat162float(h2));
            __nv_bfloat16 l3 = __float2bfloat16(v.w - __bfloat162float(h3));
            *(__nv_bfloat162*)&sA_hi[row * SSTR + c4]     = __halves2bfloat162(h0, h1);
            *(__nv_bfloat162*)&sA_hi[row * SSTR + c4 + 2] = __halves2bfloat162(h2, h3);
            *(__nv_bfloat162*)&sA_lo[row * SSTR + c4]     = __halves2bfloat162(l0, l1);
            *(__nv_bfloat162*)&sA_lo[row * SSTR + c4 + 2] = __halves2bfloat162(l2, l3);

            float4 u = *(const float4*)(Bg + (size_t)row * K + k0 + c4);
            __nv_bfloat16 g0 = __float2bfloat16(u.x);
            __nv_bfloat16 g1 = __float2bfloat16(u.y);
            __nv_bfloat16 g2 = __float2bfloat16(u.z);
            __nv_bfloat16 g3 = __float2bfloat16(u.w);
            __nv_bfloat16 m0 = __float2bfloat16(u.x - __bfloat162float(g0));
            __nv_bfloat16 m1 = __float2bfloat16(u.y - __bfloat162float(g1));
            __nv_bfloat16 m2 = __float2bfloat16(u.z - __bfloat162float(g2));
            __nv_bfloat16 m3 = __float2bfloat16(u.w - __bfloat162float(g3));
            *(__nv_bfloat162*)&sB_hi[row * SSTR + c4]     = __halves2bfloat162(g0, g1);
            *(__nv_bfloat162*)&sB_hi[row * SSTR + c4 + 2] = __halves2bfloat162(g2, g3);
            *(__nv_bfloat162*)&sB_lo[row * SSTR + c4]     = __halves2bfloat162(m0, m1);
            *(__nv_bfloat162*)&sB_lo[row * SSTR + c4 + 2] = __halves2bfloat162(m2, m3);
        }
        __syncthreads();

#pragma unroll
        for (int kk = 0; kk < BK; kk += 16) {
            uint32_t aoff = (uint32_t)((a_row * SSTR + kk + a_k) * 2);
            uint32_t boff = (uint32_t)((b_row * SSTR + kk + b_k) * 2);
            const uint32_t mstep = 16 * SSTR * 2;

            uint32_t ah0[4], ah1[4], al0[4], al1[4];
            ldsm_x4(ah0[0], ah0[1], ah0[2], ah0[3], sAhi + aoff);
            ldsm_x4(ah1[0], ah1[1], ah1[2], ah1[3], sAhi + aoff + mstep);
            ldsm_x4(al0[0], al0[1], al0[2], al0[3], sAlo + aoff);
            ldsm_x4(al1[0], al1[1], al1[2], al1[3], sAlo + aoff + mstep);

            uint32_t bh0[4], bh1[4], bl0[4], bl1[4];
            ldsm_x4(bh0[0], bh0[1], bh0[2], bh0[3], sBhi + boff);
            ldsm_x4(bh1[0], bh1[1], bh1[2], bh1[3], sBhi + boff + mstep);
            ldsm_x4(bl0[0], bl0[1], bl0[2], bl0[3], sBlo + boff);
            ldsm_x4(bl1[0], bl1[1], bl1[2], bl1[3], sBlo + boff + mstep);

#pragma unroll
            for (int mt = 0; mt < 2; ++mt) {
                const uint32_t* aH = mt ? ah1 : ah0;
                const uint32_t* aL = mt ? al1 : al0;
#pragma unroll
                for (int nt = 0; nt < 4; ++nt) {
                    const uint32_t* bH = (nt < 2) ? bh0 : bh1;
                    const uint32_t* bL = (nt < 2) ? bl0 : bl1;
                    int p = (nt & 1) * 2;
                    float* c = acc[mt][nt];
                    mma_bf16(c, aH[0], aH[1], aH[2], aH[3], bH[p], bH[p + 1]);
                    mma_bf16(c, aL[0], aL[1], aL[2], aL[3], bH[p], bH[p + 1]);
                    mma_bf16(c, aH[0], aH[1], aH[2], aH[3], bL[p], bL[p + 1]);
                }
            }
        }
        __syncthreads();
    }

#pragma unroll
    for (int mt = 0; mt < 2; ++mt) {
#pragma unroll
        for (int nt = 0; nt < 4; ++nt) {
            int r0 = bm + wm + mt * 16 + (lane >> 2);
            int cg = bn + wn + nt * 8 + ((lane & 3) << 1);
            float b0 = bias[cg], b1 = bias[cg + 1];
            float2 o0 = make_float2(acc[mt][nt][0] + b0, acc[mt][nt][1] + b1);
            float2 o1 = make_float2(acc[mt][nt][2] + b0, acc[mt][nt][3] + b1);
            *(float2*)(C + (size_t)r0 * Nc + cg)       = o0;
            *(float2*)(C + (size_t)(r0 + 8) * Nc + cg) = o1;
        }
    }
}

// ---------------------------------------------------------------------------
// Fused GRU gate update for one timestep.
// ---------------------------------------------------------------------------
__global__ void __launch_bounds__(256)
gru_gate(const float* __restrict__ gi, const float* __restrict__ gh,
         const float* __restrict__ hprev, const float* __restrict__ mask,
         float* __restrict__ hout)
{
    int idx = blockIdx.x * 256 + threadIdx.x;      // over N_ENV * HID
    int i = idx >> 9;                              // env (HID = 512)
    int c = idx & (HID - 1);

    float m  = mask[i];
    float h  = hprev[idx] * m;

    size_t base = (size_t)i * G3 + c;
    float ir = gi[base];
    float iz = gi[base + HID];
    float in_ = gi[base + 2 * HID];
    float hr = gh[base];
    float hz = gh[base + HID];
    float hn = gh[base + 2 * HID];

    float r = 1.0f / (1.0f + __expf(-(ir + hr)));
    float z = 1.0f / (1.0f + __expf(-(iz + hz)));
    float n = tanhf(in_ + r * hn);
    hout[idx] = (1.0f - z) * n + z * h;
}

// ---------------------------------------------------------------------------
__global__ void __launch_bounds__(256)
copy_hlast(const float* __restrict__ src, float* __restrict__ dst)
{
    int idx = blockIdx.x * 256 + threadIdx.x;
    ((float4*)dst)[idx] = ((const float4*)src)[idx];
}

// ---------------------------------------------------------------------------
// In-place row LayerNorm over (T*N, H). One 128-thread block per row.
// ---------------------------------------------------------------------------
__global__ void __launch_bounds__(128)
layernorm_rows(float* __restrict__ data, const float* __restrict__ w,
               const float* __restrict__ b)
{
    __shared__ float ss[4], sqs[4];
    float* p = data + (size_t)blockIdx.x * HID;
    int t = threadIdx.x;

    float4 v = ((const float4*)p)[t];
    float s  = v.x + v.y + v.z + v.w;
    float sq = v.x * v.x + v.y * v.y + v.z * v.z + v.w * v.w;

#pragma unroll
    for (int o = 16; o > 0; o >>= 1) {
        s  += __shfl_xor_sync(0xffffffffu, s,  o);
        sq += __shfl_xor_sync(0xffffffffu, sq, o);
    }
    int warp = t >> 5;
    if ((t & 31) == 0) { ss[warp] = s; sqs[warp] = sq; }
    __syncthreads();
    s  = ss[0]  + ss[1]  + ss[2]  + ss[3];
    sq = sqs[0] + sqs[1] + sqs[2] + sqs[3];

    float mu  = s * (1.0f / HID);
    float var = sq * (1.0f / HID) - mu * mu;
    float inv = rsqrtf(var + LN_EPS);

    float4 wv = ((const float4*)w)[t];
    float4 bv = ((const float4*)b)[t];
    float4 o;
    o.x = (v.x - mu) * inv * wv.x + bv.x;
    o.y = (v.y - mu) * inv * wv.y + bv.y;
    o.z = (v.z - mu) * inv * wv.z + bv.z;
    o.w = (v.w - mu) * inv * wv.w + bv.w;
    ((float4*)p)[t] = o;
}

// ---------------------------------------------------------------------------
extern "C" void kernel_launch(void* const* d_in, const int* in_sizes, int n_in,
                              void* d_out, int out_size)
{
    const float* x     = (const float*)d_in[0];   // (T*N, IN)
    const float* hxs   = (const float*)d_in[1];   // (N, H)
    const float* masks = (const float*)d_in[2];   // (T*N, 1)
    const float* W_ih  = (const float*)d_in[3];   // (3H, IN)
    const float* W_hh  = (const float*)d_in[4];   // (3H, H)
    const float* b_ih  = (const float*)d_in[5];   // (3H,)
    const float* b_hh  = (const float*)d_in[6];   // (3H,)
    const float* ln_w  = (const float*)d_in[7];   // (H,)
    const float* ln_b  = (const float*)d_in[8];   // (H,)
    float* out = (float*)d_out;                   // (T*N*H) normed + (N*H) h_last

    float *gi, *gh;
    cudaGetSymbolAddress((void**)&gi, g_gi);
    cudaGetSymbolAddress((void**)&gh, g_gh);

    // 1) GI = x @ W_ih^T + b_ih for all T*N rows at once (tensor cores).
    {
        dim3 grid(G3 / BN, (T_STEPS * N_ENV) / BM);
        gemm_split_bf16<<<grid, 128>>>(x, W_ih, b_ih, nullptr, gi,
                                       T_STEPS * N_ENV, G3, IN_D);
    }

    // 2) Recurrent scan: per step, gh GEMM (with row mask on h) + fused gates.
    dim3 ggrid(G3 / BN, N_ENV / BM);   // 24 x 8 = 192 blocks
    const int gate_blocks = (N_ENV * HID) / 256;
    for (int t = 0; t < T_STEPS; ++t) {
        const float* hprev = (t == 0) ? hxs : (out + (size_t)(t - 1) * N_ENV * HID);
        const float* mt    = masks + (size_t)t * N_ENV;
        gemm_split_bf16<<<ggrid, 128>>>(hprev, W_hh, b_hh, mt, gh,
                                        N_ENV, G3, HID);
        gru_gate<<<gate_blocks, 256>>>(gi + (size_t)t * N_ENV * G3, gh,
                                       hprev, mt,
                                       out + (size_t)t * N_ENV * HID);
    }

    // 3) h_last (raw) to tail, before LN rewrites the rows.
    copy_hlast<<<(N_ENV * HID / 4) / 256, 256>>>(
        out + (size_t)(T_STEPS - 1) * N_ENV * HID,
        out + (size_t)T_STEPS * N_ENV * HID);

    // 4) In-place LayerNorm over all T*N rows.
    layernorm_rows<<<T_STEPS * N_ENV, 128>>>(out, ln_w, ln_b);
}

// round 4
// speedup vs baseline: 2.5963x; 1.6078x over previous
#include <cuda_runtime.h>
#include <cuda_bf16.h>
#include <cstdint>
#include <math.h>

#define T_STEPS 128
#define N_ENV   512
#define IN_D    512
#define HID     512
#define G3      (3 * HID)      // 1536
#define LN_EPS  1e-5f

// ---------------------------------------------------------------------------
// Persistent scratch (static __device__ arrays; no runtime allocation).
// ---------------------------------------------------------------------------
__device__ float g_gi[(size_t)T_STEPS * N_ENV * G3];          // 402 MB
__device__ float g_gh[(size_t)N_ENV * G3];                    // 3 MB
__device__ __nv_bfloat16 g_xh[(size_t)T_STEPS * N_ENV * IN_D]; // 67 MB
__device__ __nv_bfloat16 g_xl[(size_t)T_STEPS * N_ENV * IN_D];
__device__ __nv_bfloat16 g_wih_h[(size_t)G3 * IN_D];
__device__ __nv_bfloat16 g_wih_l[(size_t)G3 * IN_D];
__device__ __nv_bfloat16 g_whh_h[(size_t)G3 * HID];
__device__ __nv_bfloat16 g_whh_l[(size_t)G3 * HID];
__device__ __nv_bfloat16 g_hh[(size_t)N_ENV * HID];
__device__ __nv_bfloat16 g_hl[(size_t)N_ENV * HID];

// ---------------------------------------------------------------------------
// fp32 -> (hi, lo) bf16 split, vectorized.
// ---------------------------------------------------------------------------
__global__ void __launch_bounds__(256)
split_bf16(const float* __restrict__ src, __nv_bfloat16* __restrict__ hi,
           __nv_bfloat16* __restrict__ lo, int n4)
{
    int idx = blockIdx.x * 256 + threadIdx.x;
    if (idx >= n4) return;
    float4 v = ((const float4*)src)[idx];
    __nv_bfloat16 h0 = __float2bfloat16(v.x);
    __nv_bfloat16 h1 = __float2bfloat16(v.y);
    __nv_bfloat16 h2 = __float2bfloat16(v.z);
    __nv_bfloat16 h3 = __float2bfloat16(v.w);
    __nv_bfloat16 l0 = __float2bfloat16(v.x - __bfloat162float(h0));
    __nv_bfloat16 l1 = __float2bfloat16(v.y - __bfloat162float(h1));
    __nv_bfloat16 l2 = __float2bfloat16(v.z - __bfloat162float(h2));
    __nv_bfloat16 l3 = __float2bfloat16(v.w - __bfloat162float(h3));
    ((__nv_bfloat162*)hi)[2 * idx]     = __halves2bfloat162(h0, h1);
    ((__nv_bfloat162*)hi)[2 * idx + 1] = __halves2bfloat162(h2, h3);
    ((__nv_bfloat162*)lo)[2 * idx]     = __halves2bfloat162(l0, l1);
    ((__nv_bfloat162*)lo)[2 * idx + 1] = __halves2bfloat162(l2, l3);
}

// ---------------------------------------------------------------------------
// mma / ldmatrix primitives
// ---------------------------------------------------------------------------
__device__ __forceinline__ void ldsm_x4(uint32_t& r0, uint32_t& r1,
                                        uint32_t& r2, uint32_t& r3,
                                        uint32_t addr)
{
    asm volatile("ldmatrix.sync.aligned.m8n8.x4.shared.b16 {%0,%1,%2,%3}, [%4];\n"
                 : "=r"(r0), "=r"(r1), "=r"(r2), "=r"(r3) : "r"(addr));
}

__device__ __forceinline__ void mma_bf16(float* c, const uint32_t* a,
                                         uint32_t b0, uint32_t b1)
{
    asm volatile("mma.sync.aligned.m16n8k16.row.col.f32.bf16.bf16.f32 "
                 "{%0,%1,%2,%3},{%4,%5,%6,%7},{%8,%9},{%0,%1,%2,%3};\n"
                 : "+f"(c[0]), "+f"(c[1]), "+f"(c[2]), "+f"(c[3])
                 : "r"(a[0]), "r"(a[1]), "r"(a[2]), "r"(a[3]), "r"(b0), "r"(b1));
}

// ===========================================================================
// Pre-split 3-term bf16 GEMM:
//   C[M,Nc] = diag(rowmask) * (Ah+Al)[M,K] @ (Bh+Bl)[Nc,K]^T + bias
//   (computed as Ah*Bh + Al*Bh + Ah*Bl, fp32 accumulate)
// CTA: 128 threads. BM_ in {64, 32}; BN=64; BK=64.
//   BM_=64: 4 warps in 2x2, warp tile 32x32 (NW_=32)
//   BM_=32: 4 warps in 1x4, warp tile 32x16 (NW_=16)
// ===========================================================================
#define BKQ  64
#define SSTQ 72   // smem row stride in bf16 (144 B -> conflict-free ldmatrix)

template<int BM_, int NW_>
__global__ void __launch_bounds__(128)
gemm_presplit(const __nv_bfloat16* __restrict__ Ah, const __nv_bfloat16* __restrict__ Al,
              const __nv_bfloat16* __restrict__ Bh, const __nv_bfloat16* __restrict__ Bl,
              const float* __restrict__ bias, const float* __restrict__ rowmask,
              float* __restrict__ C, int M, int Nc, int K)
{
    constexpr int NT = NW_ / 8;       // n8 tiles per warp (4 or 2)
    constexpr int AI = BM_ / 16;      // A staging iterations

    __shared__ __nv_bfloat16 sAh[BM_ * SSTQ], sAl[BM_ * SSTQ];
    __shared__ __nv_bfloat16 sBh[64 * SSTQ],  sBl[64 * SSTQ];

    const int tid  = threadIdx.x;
    const int w    = tid >> 5;
    const int lane = tid & 31;
    const int bm   = blockIdx.y * BM_;
    const int bn   = blockIdx.x * 64;
    const int wm   = (NW_ == 32) ? (w & 1) * 32 : 0;
    const int wn   = (NW_ == 32) ? (w >> 1) * 32 : w * 16;

    float acc[2][NT][4];
#pragma unroll
    for (int i = 0; i < 2; ++i)
#pragma unroll
        for (int j = 0; j < NT; ++j)
#pragma unroll
            for (int k = 0; k < 4; ++k) acc[i][j][k] = 0.0f;

    bool alive[AI];
#pragma unroll
    for (int i = 0; i < AI; ++i) {
        int row = (tid + i * 128) >> 3;
        alive[i] = rowmask ? (rowmask[bm + row] != 0.0f) : true;
    }

    const uint32_t sAhB = (uint32_t)__cvta_generic_to_shared(sAh);
    const uint32_t sAlB = (uint32_t)__cvta_generic_to_shared(sAl);
    const uint32_t sBhB = (uint32_t)__cvta_generic_to_shared(sBh);
    const uint32_t sBlB = (uint32_t)__cvta_generic_to_shared(sBl);

    const int a_row = wm + (lane & 7) + ((lane >> 3) & 1) * 8;
    const int a_k   = (lane >> 4) << 3;
    const int b_row = wn + (lane & 7) + ((lane >> 4) << 3);
    const int b_k   = ((lane >> 3) & 1) << 3;

    for (int k0 = 0; k0 < K; k0 += BKQ) {
        // ---- stage A (pre-split bf16, mask by zeroing dead rows) ----
#pragma unroll
        for (int i = 0; i < AI; ++i) {
            int idx = tid + i * 128;
            int row = idx >> 3;
            int kc  = (idx & 7) << 3;
            size_t gofs = (size_t)(bm + row) * K + k0 + kc;
            uint4 vh = *(const uint4*)(Ah + gofs);
            uint4 vl = *(const uint4*)(Al + gofs);
            if (!alive[i]) { vh = make_uint4(0,0,0,0); vl = make_uint4(0,0,0,0); }
            int s = row * SSTQ + kc;
            *(uint2*)&sAh[s]     = make_uint2(vh.x, vh.y);
            *(uint2*)&sAh[s + 4] = make_uint2(vh.z, vh.w);
            *(uint2*)&sAl[s]     = make_uint2(vl.x, vl.y);
            *(uint2*)&sAl[s + 4] = make_uint2(vl.z, vl.w);
        }
        // ---- stage B ----
#pragma unroll
        for (int i = 0; i < 4; ++i) {
            int idx = tid + i * 128;
            int row = idx >> 3;
            int kc  = (idx & 7) << 3;
            size_t gofs = (size_t)(bn + row) * K + k0 + kc;
            uint4 vh = *(const uint4*)(Bh + gofs);
            uint4 vl = *(const uint4*)(Bl + gofs);
            int s = row * SSTQ + kc;
            *(uint2*)&sBh[s]     = make_uint2(vh.x, vh.y);
            *(uint2*)&sBh[s + 4] = make_uint2(vh.z, vh.w);
            *(uint2*)&sBl[s]     = make_uint2(vl.x, vl.y);
            *(uint2*)&sBl[s + 4] = make_uint2(vl.z, vl.w);
        }
        __syncthreads();

#pragma unroll
        for (int kk = 0; kk < BKQ; kk += 16) {
            const uint32_t mstep = 16 * SSTQ * 2;
            uint32_t aoff = (uint32_t)((a_row * SSTQ + kk + a_k) * 2);
            uint32_t boff = (uint32_t)((b_row * SSTQ + kk + b_k) * 2);

            uint32_t ah0[4], ah1[4], al0[4], al1[4];
            ldsm_x4(ah0[0], ah0[1], ah0[2], ah0[3], sAhB + aoff);
            ldsm_x4(ah1[0], ah1[1], ah1[2], ah1[3], sAhB + aoff + mstep);
            ldsm_x4(al0[0], al0[1], al0[2], al0[3], sAlB + aoff);
            ldsm_x4(al1[0], al1[1], al1[2], al1[3], sAlB + aoff + mstep);

            uint32_t bh0[4], bl0[4];
            uint32_t bh1[4], bl1[4];
            ldsm_x4(bh0[0], bh0[1], bh0[2], bh0[3], sBhB + boff);
            ldsm_x4(bl0[0], bl0[1], bl0[2], bl0[3], sBlB + boff);
            if (NT == 4) {
                ldsm_x4(bh1[0], bh1[1], bh1[2], bh1[3], sBhB + boff + mstep);
                ldsm_x4(bl1[0], bl1[1], bl1[2], bl1[3], sBlB + boff + mstep);
            }

#pragma unroll
            for (int mt = 0; mt < 2; ++mt) {
                const uint32_t* aH = mt ? ah1 : ah0;
                const uint32_t* aL = mt ? al1 : al0;
#pragma unroll
                for (int nt = 0; nt < NT; ++nt) {
                    const uint32_t* bH = (nt < 2) ? bh0 : bh1;
                    const uint32_t* bL = (nt < 2) ? bl0 : bl1;
                    int p = (nt & 1) * 2;
                    float* c = acc[mt][nt];
                    mma_bf16(c, aH, bH[p], bH[p + 1]);
                    mma_bf16(c, aL, bH[p], bH[p + 1]);
                    mma_bf16(c, aH, bL[p], bL[p + 1]);
                }
            }
        }
        __syncthreads();
    }

    // ---- epilogue ----
#pragma unroll
    for (int mt = 0; mt < 2; ++mt) {
#pragma unroll
        for (int nt = 0; nt < NT; ++nt) {
            int r0 = bm + wm + mt * 16 + (lane >> 2);
            int cg = bn + wn + nt * 8 + ((lane & 3) << 1);
            float b0 = bias[cg], b1 = bias[cg + 1];
            float2 o0 = make_float2(acc[mt][nt][0] + b0, acc[mt][nt][1] + b1);
            float2 o1 = make_float2(acc[mt][nt][2] + b0, acc[mt][nt][3] + b1);
            *(float2*)(C + (size_t)r0 * Nc + cg)       = o0;
            *(float2*)(C + (size_t)(r0 + 8) * Nc + cg) = o1;
        }
    }
}

// ---------------------------------------------------------------------------
// Fused GRU gate update; also emits pre-split h for the next step's GEMM.
// ---------------------------------------------------------------------------
__global__ void __launch_bounds__(256)
gru_gate_split(const float* __restrict__ gi, const float* __restrict__ gh,
               const float* __restrict__ hprev, const float* __restrict__ mask,
               float* __restrict__ hout,
               __nv_bfloat16* __restrict__ hhi, __nv_bfloat16* __restrict__ hlo)
{
    int idx = blockIdx.x * 256 + threadIdx.x;      // over N_ENV * HID
    int i = idx >> 9;
    int c = idx & (HID - 1);

    float m  = mask[i];
    float h  = hprev[idx] * m;

    size_t base = (size_t)i * G3 + c;
    float ir  = gi[base];
    float iz  = gi[base + HID];
    float in_ = gi[base + 2 * HID];
    float hr  = gh[base];
    float hz  = gh[base + HID];
    float hn  = gh[base + 2 * HID];

    float r = 1.0f / (1.0f + __expf(-(ir + hr)));
    float z = 1.0f / (1.0f + __expf(-(iz + hz)));
    float n = tanhf(in_ + r * hn);
    float hnew = (1.0f - z) * n + z * h;

    hout[idx] = hnew;
    __nv_bfloat16 hi = __float2bfloat16(hnew);
    hhi[idx] = hi;
    hlo[idx] = __float2bfloat16(hnew - __bfloat162float(hi));
}

// ---------------------------------------------------------------------------
__global__ void __launch_bounds__(256)
copy_hlast(const float* __restrict__ src, float* __restrict__ dst)
{
    int idx = blockIdx.x * 256 + threadIdx.x;
    ((float4*)dst)[idx] = ((const float4*)src)[idx];
}

// ---------------------------------------------------------------------------
// In-place row LayerNorm over (T*N, H). One 128-thread block per row.
// ---------------------------------------------------------------------------
__global__ void __launch_bounds__(128)
layernorm_rows(float* __restrict__ data, const float* __restrict__ w,
               const float* __restrict__ b)
{
    __shared__ float ss[4], sqs[4];
    float* p = data + (size_t)blockIdx.x * HID;
    int t = threadIdx.x;

    float4 v = ((const float4*)p)[t];
    float s  = v.x + v.y + v.z + v.w;
    float sq = v.x * v.x + v.y * v.y + v.z * v.z + v.w * v.w;

#pragma unroll
    for (int o = 16; o > 0; o >>= 1) {
        s  += __shfl_xor_sync(0xffffffffu, s,  o);
        sq += __shfl_xor_sync(0xffffffffu, sq, o);
    }
    int warp = t >> 5;
    if ((t & 31) == 0) { ss[warp] = s; sqs[warp] = sq; }
    __syncthreads();
    s  = ss[0]  + ss[1]  + ss[2]  + ss[3];
    sq = sqs[0] + sqs[1] + sqs[2] + sqs[3];

    float mu  = s * (1.0f / HID);
    float var = sq * (1.0f / HID) - mu * mu;
    float inv = rsqrtf(var + LN_EPS);

    float4 wv = ((const float4*)w)[t];
    float4 bv = ((const float4*)b)[t];
    float4 o;
    o.x = (v.x - mu) * inv * wv.x + bv.x;
    o.y = (v.y - mu) * inv * wv.y + bv.y;
    o.z = (v.z - mu) * inv * wv.z + bv.z;
    o.w = (v.w - mu) * inv * wv.w + bv.w;
    ((float4*)p)[t] = o;
}

// ---------------------------------------------------------------------------
extern "C" void kernel_launch(void* const* d_in, const int* in_sizes, int n_in,
                              void* d_out, int out_size)
{
    const float* x     = (const float*)d_in[0];   // (T*N, IN)
    const float* hxs   = (const float*)d_in[1];   // (N, H)
    const float* masks = (const float*)d_in[2];   // (T*N, 1)
    const float* W_ih  = (const float*)d_in[3];   // (3H, IN)
    const float* W_hh  = (const float*)d_in[4];   // (3H, H)
    const float* b_ih  = (const float*)d_in[5];   // (3H,)
    const float* b_hh  = (const float*)d_in[6];   // (3H,)
    const float* ln_w  = (const float*)d_in[7];   // (H,)
    const float* ln_b  = (const float*)d_in[8];   // (H,)
    float* out = (float*)d_out;                   // (T*N*H) normed + (N*H) h_last

    float *gi, *gh;
    __nv_bfloat16 *xh, *xl, *wih_h, *wih_l, *whh_h, *whh_l, *hh, *hl;
    cudaGetSymbolAddress((void**)&gi, g_gi);
    cudaGetSymbolAddress((void**)&gh, g_gh);
    cudaGetSymbolAddress((void**)&xh, g_xh);
    cudaGetSymbolAddress((void**)&xl, g_xl);
    cudaGetSymbolAddress((void**)&wih_h, g_wih_h);
    cudaGetSymbolAddress((void**)&wih_l, g_wih_l);
    cudaGetSymbolAddress((void**)&whh_h, g_whh_h);
    cudaGetSymbolAddress((void**)&whh_l, g_whh_l);
    cudaGetSymbolAddress((void**)&hh, g_hh);
    cudaGetSymbolAddress((void**)&hl, g_hl);

    // 0) One-time fp32 -> split-bf16 conversions.
    {
        int n4;
        n4 = T_STEPS * N_ENV * IN_D / 4;
        split_bf16<<<(n4 + 255) / 256, 256>>>(x, xh, xl, n4);
        n4 = G3 * IN_D / 4;
        split_bf16<<<(n4 + 255) / 256, 256>>>(W_ih, wih_h, wih_l, n4);
        n4 = G3 * HID / 4;
        split_bf16<<<(n4 + 255) / 256, 256>>>(W_hh, whh_h, whh_l, n4);
        n4 = N_ENV * HID / 4;
        split_bf16<<<(n4 + 255) / 256, 256>>>(hxs, hh, hl, n4);
    }

    // 1) GI = x @ W_ih^T + b_ih for all T*N rows (tensor cores, BM=64).
    {
        dim3 grid(G3 / 64, (T_STEPS * N_ENV) / 64);
        gemm_presplit<64, 32><<<grid, 128>>>(xh, xl, wih_h, wih_l, b_ih,
                                             nullptr, gi,
                                             T_STEPS * N_ENV, G3, IN_D);
    }

    // 2) Recurrent scan (BM=32 -> 384 CTAs per step).
    dim3 ggrid(G3 / 64, N_ENV / 32);
    const int gate_blocks = (N_ENV * HID) / 256;
    for (int t = 0; t < T_STEPS; ++t) {
        const float* hprev = (t == 0) ? hxs : (out + (size_t)(t - 1) * N_ENV * HID);
        const float* mt    = masks + (size_t)t * N_ENV;
        gemm_presplit<32, 16><<<ggrid, 128>>>(hh, hl, whh_h, whh_l, b_hh,
                                              mt, gh, N_ENV, G3, HID);
        gru_gate_split<<<gate_blocks, 256>>>(gi + (size_t)t * N_ENV * G3, gh,
                                             hprev, mt,
                                             out + (size_t)t * N_ENV * HID,
                                             hh, hl);
    }

    // 3) h_last (raw) to tail before LN rewrites rows.
    copy_hlast<<<(N_ENV * HID / 4) / 256, 256>>>(
        out + (size_t)(T_STEPS - 1) * N_ENV * HID,
        out + (size_t)T_STEPS * N_ENV * HID);

    // 4) In-place LayerNorm over all T*N rows.
    layernorm_rows<<<T_STEPS * N_ENV, 128>>>(out, ln_w, ln_b);
}

// round 5
// speedup vs baseline: 2.7532x; 1.0604x over previous
#include <cuda_runtime.h>
#include <cuda_bf16.h>
#include <cstdint>
#include <math.h>

#define T_STEPS 128
#define N_ENV   512
#define IN_D    512
#define HID     512
#define G3      (3 * HID)      // 1536
#define LN_EPS  1e-5f
#define SCAN_CTAS 128

// ---------------------------------------------------------------------------
// Persistent scratch (static __device__ arrays; no runtime allocation).
// ---------------------------------------------------------------------------
__device__ float g_gi[(size_t)T_STEPS * N_ENV * G3];            // 402 MB
__device__ __nv_bfloat16 g_xh[(size_t)T_STEPS * N_ENV * IN_D];  // 67 MB
__device__ __nv_bfloat16 g_xl[(size_t)T_STEPS * N_ENV * IN_D];
__device__ __nv_bfloat16 g_wih_h[(size_t)G3 * IN_D];
__device__ __nv_bfloat16 g_wih_l[(size_t)G3 * IN_D];
__device__ __nv_bfloat16 g_whh_h[(size_t)G3 * HID];
__device__ __nv_bfloat16 g_whh_l[(size_t)G3 * HID];
__device__ __nv_bfloat16 g_h0h[(size_t)N_ENV * HID];   // ping-pong split h
__device__ __nv_bfloat16 g_h0l[(size_t)N_ENV * HID];
__device__ __nv_bfloat16 g_h1h[(size_t)N_ENV * HID];
__device__ __nv_bfloat16 g_h1l[(size_t)N_ENV * HID];
__device__ unsigned g_bar;

// ---------------------------------------------------------------------------
// fp32 -> (hi, lo) bf16 split, vectorized.
// ---------------------------------------------------------------------------
__global__ void __launch_bounds__(256)
split_bf16(const float* __restrict__ src, __nv_bfloat16* __restrict__ hi,
           __nv_bfloat16* __restrict__ lo, int n4)
{
    int idx = blockIdx.x * 256 + threadIdx.x;
    if (idx >= n4) return;
    float4 v = ((const float4*)src)[idx];
    __nv_bfloat16 h0 = __float2bfloat16(v.x);
    __nv_bfloat16 h1 = __float2bfloat16(v.y);
    __nv_bfloat16 h2 = __float2bfloat16(v.z);
    __nv_bfloat16 h3 = __float2bfloat16(v.w);
    __nv_bfloat16 l0 = __float2bfloat16(v.x - __bfloat162float(h0));
    __nv_bfloat16 l1 = __float2bfloat16(v.y - __bfloat162float(h1));
    __nv_bfloat16 l2 = __float2bfloat16(v.z - __bfloat162float(h2));
    __nv_bfloat16 l3 = __float2bfloat16(v.w - __bfloat162float(h3));
    ((__nv_bfloat162*)hi)[2 * idx]     = __halves2bfloat162(h0, h1);
    ((__nv_bfloat162*)hi)[2 * idx + 1] = __halves2bfloat162(h2, h3);
    ((__nv_bfloat162*)lo)[2 * idx]     = __halves2bfloat162(l0, l1);
    ((__nv_bfloat162*)lo)[2 * idx + 1] = __halves2bfloat162(l2, l3);
}

// ---------------------------------------------------------------------------
// mma / ldmatrix primitives
// ---------------------------------------------------------------------------
__device__ __forceinline__ void ldsm_x4(uint32_t& r0, uint32_t& r1,
                                        uint32_t& r2, uint32_t& r3,
                                        uint32_t addr)
{
    asm volatile("ldmatrix.sync.aligned.m8n8.x4.shared.b16 {%0,%1,%2,%3}, [%4];\n"
                 : "=r"(r0), "=r"(r1), "=r"(r2), "=r"(r3) : "r"(addr));
}

__device__ __forceinline__ void mma_bf16(float* c, const uint32_t* a,
                                         uint32_t b0, uint32_t b1)
{
    asm volatile("mma.sync.aligned.m16n8k16.row.col.f32.bf16.bf16.f32 "
                 "{%0,%1,%2,%3},{%4,%5,%6,%7},{%8,%9},{%0,%1,%2,%3};\n"
                 : "+f"(c[0]), "+f"(c[1]), "+f"(c[2]), "+f"(c[3])
                 : "r"(a[0]), "r"(a[1]), "r"(a[2]), "r"(a[3]), "r"(b0), "r"(b1));
}

// ===========================================================================
// GI GEMM (same as R4): C = A@B^T + bias, pre-split 3-term bf16.
// CTA 64x64, 4 warps of 32x32, BK=64.
// ===========================================================================
#define SSTQ 72

__global__ void __launch_bounds__(128)
gemm_gi(const __nv_bfloat16* __restrict__ Ah, const __nv_bfloat16* __restrict__ Al,
        const __nv_bfloat16* __restrict__ Bh, const __nv_bfloat16* __restrict__ Bl,
        const float* __restrict__ bias, float* __restrict__ C, int Nc, int K)
{
    __shared__ __nv_bfloat16 sAh[64 * SSTQ], sAl[64 * SSTQ];
    __shared__ __nv_bfloat16 sBh[64 * SSTQ], sBl[64 * SSTQ];

    const int tid  = threadIdx.x;
    const int w    = tid >> 5;
    const int lane = tid & 31;
    const int bm   = blockIdx.y * 64;
    const int bn   = blockIdx.x * 64;
    const int wm   = (w & 1) * 32;
    const int wn   = (w >> 1) * 32;

    float acc[2][4][4];
#pragma unroll
    for (int i = 0; i < 2; ++i)
#pragma unroll
        for (int j = 0; j < 4; ++j)
#pragma unroll
            for (int k = 0; k < 4; ++k) acc[i][j][k] = 0.0f;

    const uint32_t sAhB = (uint32_t)__cvta_generic_to_shared(sAh);
    const uint32_t sAlB = (uint32_t)__cvta_generic_to_shared(sAl);
    const uint32_t sBhB = (uint32_t)__cvta_generic_to_shared(sBh);
    const uint32_t sBlB = (uint32_t)__cvta_generic_to_shared(sBl);

    const int a_row = wm + (lane & 7) + ((lane >> 3) & 1) * 8;
    const int a_k   = (lane >> 4) << 3;
    const int b_row = wn + (lane & 7) + ((lane >> 4) << 3);
    const int b_k   = ((lane >> 3) & 1) << 3;

    for (int k0 = 0; k0 < K; k0 += 64) {
#pragma unroll
        for (int i = 0; i < 4; ++i) {
            int idx = tid + i * 128;
            int row = idx >> 3;
            int kc  = (idx & 7) << 3;
            size_t ga = (size_t)(bm + row) * K + k0 + kc;
            size_t gb = (size_t)(bn + row) * K + k0 + kc;
            uint4 vh = *(const uint4*)(Ah + ga);
            uint4 vl = *(const uint4*)(Al + ga);
            int s = row * SSTQ + kc;
            *(uint2*)&sAh[s]     = make_uint2(vh.x, vh.y);
            *(uint2*)&sAh[s + 4] = make_uint2(vh.z, vh.w);
            *(uint2*)&sAl[s]     = make_uint2(vl.x, vl.y);
            *(uint2*)&sAl[s + 4] = make_uint2(vl.z, vl.w);
            uint4 wh = *(const uint4*)(Bh + gb);
            uint4 wl = *(const uint4*)(Bl + gb);
            *(uint2*)&sBh[s]     = make_uint2(wh.x, wh.y);
            *(uint2*)&sBh[s + 4] = make_uint2(wh.z, wh.w);
            *(uint2*)&sBl[s]     = make_uint2(wl.x, wl.y);
            *(uint2*)&sBl[s + 4] = make_uint2(wl.z, wl.w);
        }
        __syncthreads();

#pragma unroll
        for (int kk = 0; kk < 64; kk += 16) {
            const uint32_t mstep = 16 * SSTQ * 2;
            uint32_t aoff = (uint32_t)((a_row * SSTQ + kk + a_k) * 2);
            uint32_t boff = (uint32_t)((b_row * SSTQ + kk + b_k) * 2);

            uint32_t ah0[4], ah1[4], al0[4], al1[4];
            ldsm_x4(ah0[0], ah0[1], ah0[2], ah0[3], sAhB + aoff);
            ldsm_x4(ah1[0], ah1[1], ah1[2], ah1[3], sAhB + aoff + mstep);
            ldsm_x4(al0[0], al0[1], al0[2], al0[3], sAlB + aoff);
            ldsm_x4(al1[0], al1[1], al1[2], al1[3], sAlB + aoff + mstep);

            uint32_t bh0[4], bh1[4], bl0[4], bl1[4];
            ldsm_x4(bh0[0], bh0[1], bh0[2], bh0[3], sBhB + boff);
            ldsm_x4(bh1[0], bh1[1], bh1[2], bh1[3], sBhB + boff + mstep);
            ldsm_x4(bl0[0], bl0[1], bl0[2], bl0[3], sBlB + boff);
            ldsm_x4(bl1[0], bl1[1], bl1[2], bl1[3], sBlB + boff + mstep);

#pragma unroll
            for (int mt = 0; mt < 2; ++mt) {
                const uint32_t* aH = mt ? ah1 : ah0;
                const uint32_t* aL = mt ? al1 : al0;
#pragma unroll
                for (int nt = 0; nt < 4; ++nt) {
                    const uint32_t* bH = (nt < 2) ? bh0 : bh1;
                    const uint32_t* bL = (nt < 2) ? bl0 : bl1;
                    int p = (nt & 1) * 2;
                    float* c = acc[mt][nt];
                    mma_bf16(c, aH, bH[p], bH[p + 1]);
                    mma_bf16(c, aL, bH[p], bH[p + 1]);
                    mma_bf16(c, aH, bL[p], bL[p + 1]);
                }
            }
        }
        __syncthreads();
    }

#pragma unroll
    for (int mt = 0; mt < 2; ++mt) {
#pragma unroll
        for (int nt = 0; nt < 4; ++nt) {
            int r0 = bm + wm + mt * 16 + (lane >> 2);
            int cg = bn + wn + nt * 8 + ((lane & 3) << 1);
            float b0 = bias[cg], b1 = bias[cg + 1];
            float2 o0 = make_float2(acc[mt][nt][0] + b0, acc[mt][nt][1] + b1);
            float2 o1 = make_float2(acc[mt][nt][2] + b0, acc[mt][nt][3] + b1);
            *(float2*)(C + (size_t)r0 * Nc + cg)       = o0;
            *(float2*)(C + (size_t)(r0 + 8) * Nc + cg) = o1;
        }
    }
}

// ===========================================================================
// Persistent fused GRU scan.
// Grid: (16 colgroups, 8 envgroups) = 128 CTAs x 256 threads.
// Each CTA: W_hh slice (96 rows x 512 K, hi+lo) resident in smem the whole
// kernel; per step: gh tile via 3-term bf16 mma, gate fused in registers,
// h ping-pong (split bf16) + fp32 out; grid barrier between steps.
// ===========================================================================
#define WSTR 520   // W smem row stride (elems); 1040B -> conflict-free ldmatrix
#define HSTR 72    // h chunk smem row stride
#define SM_WH   0
#define SM_WL   (96 * WSTR)                 // elem offsets
#define SM_HH   (2 * 96 * WSTR)
#define SM_HL   (2 * 96 * WSTR + 64 * HSTR)
#define SMEM_ELEMS (2 * 96 * WSTR + 2 * 64 * HSTR)

__global__ void __launch_bounds__(256)
gru_scan(const float* __restrict__ gi_all, const float* __restrict__ masks,
         const float* __restrict__ hxs, const float* __restrict__ b_hh,
         float* __restrict__ out,
         __nv_bfloat16* __restrict__ h0h, __nv_bfloat16* __restrict__ h0l,
         __nv_bfloat16* __restrict__ h1h, __nv_bfloat16* __restrict__ h1l)
{
    extern __shared__ __nv_bfloat16 sm[];
    __nv_bfloat16* sWh = sm + SM_WH;
    __nv_bfloat16* sWl = sm + SM_WL;
    __nv_bfloat16* sHh = sm + SM_HH;
    __nv_bfloat16* sHl = sm + SM_HL;

    const int tid  = threadIdx.x;
    const int w    = tid >> 5;
    const int lane = tid & 31;
    const int wq   = w >> 1;         // env group 0..3 (16 envs each)
    const int wr   = w & 1;          // col group 0..1 (16 cols each)
    const int c0   = blockIdx.x * 32;    // col base within HID
    const int bm   = blockIdx.y * 64;    // env base

    const uint32_t sWhB = (uint32_t)__cvta_generic_to_shared(sWh);
    const uint32_t sWlB = (uint32_t)__cvta_generic_to_shared(sWl);
    const uint32_t sHhB = (uint32_t)__cvta_generic_to_shared(sHh);
    const uint32_t sHlB = (uint32_t)__cvta_generic_to_shared(sHl);

    // ---- stage W_hh slice once: rows ch*512 + c0 + c (96 rows x 512 K) ----
    for (int i = tid; i < 96 * 64; i += 256) {
        int row = i >> 6;            // 0..95
        int seg = (i & 63) << 3;     // 0..504 step 8
        int ch  = row >> 5;
        int c   = row & 31;
        size_t g = (size_t)(ch * HID + c0 + c) * HID + seg;
        *(uint4*)&sWh[row * WSTR + seg] = *(const uint4*)&g_whh_h[g];
        *(uint4*)&sWl[row * WSTR + seg] = *(const uint4*)&g_whh_l[g];
    }

    // ---- per-thread fixed coordinates ----
    const int env0 = bm + wq * 16 + (lane >> 2);
    const int env1 = env0 + 8;
    const int colbase = c0 + wr * 16;

    // bias + h_prev registers
    float bh[3][2][2], hprev[2][2][2];
#pragma unroll
    for (int ch = 0; ch < 3; ++ch)
#pragma unroll
        for (int nt = 0; nt < 2; ++nt) {
            int col = colbase + nt * 8 + ((lane & 3) << 1);
            bh[ch][nt][0] = b_hh[ch * HID + col];
            bh[ch][nt][1] = b_hh[ch * HID + col + 1];
        }
#pragma unroll
    for (int e = 0; e < 2; ++e)
#pragma unroll
        for (int nt = 0; nt < 2; ++nt) {
            int env = e ? env1 : env0;
            int col = colbase + nt * 8 + ((lane & 3) << 1);
            float2 v = *(const float2*)&hxs[(size_t)env * HID + col];
            hprev[e][nt][0] = v.x; hprev[e][nt][1] = v.y;
        }

    // ldmatrix addressing
    const int a_row = wq * 16 + (lane & 7) + (((lane >> 3) & 1) << 3);
    const int a_k   = (lane >> 4) << 3;
    const int b_rowL = wr * 16 + (lane & 7) + ((lane >> 4) << 3);
    const int b_k   = ((lane >> 3) & 1) << 3;

    // h staging coordinates (fixed)
    const int st_row = tid >> 2;              // 0..63
    const int st_seg = (tid & 3) << 4;        // 0,16,32,48

    __syncthreads();

    for (int t = 0; t < T_STEPS; ++t) {
        const __nv_bfloat16* Rh = (t & 1) ? h1h : h0h;
        const __nv_bfloat16* Rl = (t & 1) ? h1l : h0l;
        __nv_bfloat16* Wrh = (t & 1) ? h0h : h1h;
        __nv_bfloat16* Wrl = (t & 1) ? h0l : h1l;
        const float* mrow_p = masks + (size_t)t * N_ENV;

        float m_st = mrow_p[bm + st_row];
        float m_e0 = mrow_p[env0];
        float m_e1 = mrow_p[env1];

        float acc[3][2][4];
#pragma unroll
        for (int ch = 0; ch < 3; ++ch)
#pragma unroll
            for (int nt = 0; nt < 2; ++nt)
#pragma unroll
                for (int j = 0; j < 4; ++j) acc[ch][nt][j] = 0.0f;

        for (int k0 = 0; k0 < HID; k0 += 64) {
            // stage h chunk (64 envs x 64 k), mask-zero dead rows
            {
                size_t g = (size_t)(bm + st_row) * HID + k0 + st_seg;
                uint4 vh0 = *(const uint4*)&Rh[g];
                uint4 vh1 = *(const uint4*)&Rh[g + 8];
                uint4 vl0 = *(const uint4*)&Rl[g];
                uint4 vl1 = *(const uint4*)&Rl[g + 8];
                if (m_st == 0.0f) {
                    vh0 = make_uint4(0,0,0,0); vh1 = vh0;
                    vl0 = vh0; vl1 = vh0;
                }
                int s = st_row * HSTR + st_seg;
                *(uint4*)&sHh[s]     = vh0;
                *(uint4*)&sHh[s + 8] = vh1;
                *(uint4*)&sHl[s]     = vl0;
                *(uint4*)&sHl[s + 8] = vl1;
            }
            __syncthreads();

#pragma unroll
            for (int kk = 0; kk < 64; kk += 16) {
                uint32_t aoff = (uint32_t)((a_row * HSTR + kk + a_k) * 2);
                uint32_t ah[4], al[4];
                ldsm_x4(ah[0], ah[1], ah[2], ah[3], sHhB + aoff);
                ldsm_x4(al[0], al[1], al[2], al[3], sHlB + aoff);

#pragma unroll
                for (int ch = 0; ch < 3; ++ch) {
                    uint32_t boff = (uint32_t)(((ch * 32 + b_rowL) * WSTR
                                               + k0 + kk + b_k) * 2);
                    uint32_t bhk[4], blk[4];
                    ldsm_x4(bhk[0], bhk[1], bhk[2], bhk[3], sWhB + boff);
                    ldsm_x4(blk[0], blk[1], blk[2], blk[3], sWlB + boff);
#pragma unroll
                    for (int nt = 0; nt < 2; ++nt) {
                        int p = nt * 2;
                        float* c = acc[ch][nt];
                        mma_bf16(c, ah, bhk[p], bhk[p + 1]);
                        mma_bf16(c, al, bhk[p], bhk[p + 1]);
                        mma_bf16(c, ah, blk[p], blk[p + 1]);
                    }
                }
            }
            __syncthreads();
        }

        // ---- fused gate (registers) ----
        const float* gip = gi_all + (size_t)t * N_ENV * G3;
#pragma unroll
        for (int e = 0; e < 2; ++e) {
            int env = e ? env1 : env0;
            float m = e ? m_e1 : m_e0;
#pragma unroll
            for (int nt = 0; nt < 2; ++nt) {
                int col = colbase + nt * 8 + ((lane & 3) << 1);
                size_t gb = (size_t)env * G3 + col;
                float2 gr = *(const float2*)&gip[gb];
                float2 gz = *(const float2*)&gip[gb + HID];
                float2 gn = *(const float2*)&gip[gb + 2 * HID];
                int j0 = 2 * e;

                float hr0 = acc[0][nt][j0]     + bh[0][nt][0];
                float hr1 = acc[0][nt][j0 + 1] + bh[0][nt][1];
                float hz0 = acc[1][nt][j0]     + bh[1][nt][0];
                float hz1 = acc[1][nt][j0 + 1] + bh[1][nt][1];
                float hn0 = acc[2][nt][j0]     + bh[2][nt][0];
                float hn1 = acc[2][nt][j0 + 1] + bh[2][nt][1];

                float r0 = 1.0f / (1.0f + __expf(-(gr.x + hr0)));
                float r1 = 1.0f / (1.0f + __expf(-(gr.y + hr1)));
                float z0 = 1.0f / (1.0f + __expf(-(gz.x + hz0)));
                float z1 = 1.0f / (1.0f + __expf(-(gz.y + hz1)));
                float n0 = tanhf(gn.x + r0 * hn0);
                float n1 = tanhf(gn.y + r1 * hn1);

                float h0 = hprev[e][nt][0] * m;
                float h1 = hprev[e][nt][1] * m;
                float hw0 = (1.0f - z0) * n0 + z0 * h0;
                float hw1 = (1.0f - z1) * n1 + z1 * h1;
                hprev[e][nt][0] = hw0;
                hprev[e][nt][1] = hw1;

                *(float2*)&out[(size_t)t * N_ENV * HID + (size_t)env * HID + col]
                    = make_float2(hw0, hw1);

                __nv_bfloat16 s0 = __float2bfloat16(hw0);
                __nv_bfloat16 s1 = __float2bfloat16(hw1);
                *(__nv_bfloat162*)&Wrh[(size_t)env * HID + col]
                    = __halves2bfloat162(s0, s1);
                *(__nv_bfloat162*)&Wrl[(size_t)env * HID + col]
                    = __halves2bfloat162(
                        __float2bfloat16(hw0 - __bfloat162float(s0)),
                        __float2bfloat16(hw1 - __bfloat162float(s1)));
            }
        }

        // ---- grid barrier (skip after final step) ----
        if (t < T_STEPS - 1) {
            __threadfence();
            __syncthreads();
            if (tid == 0) {
                atomicAdd(&g_bar, 1u);
                unsigned target = (unsigned)SCAN_CTAS * (unsigned)(t + 1);
                while (*(volatile unsigned*)&g_bar < target) { }
            }
            __syncthreads();
            __threadfence();
        }
    }
}

// ---------------------------------------------------------------------------
__global__ void __launch_bounds__(256)
copy_hlast(const float* __restrict__ src, float* __restrict__ dst)
{
    int idx = blockIdx.x * 256 + threadIdx.x;
    ((float4*)dst)[idx] = ((const float4*)src)[idx];
}

// ---------------------------------------------------------------------------
__global__ void __launch_bounds__(128)
layernorm_rows(float* __restrict__ data, const float* __restrict__ w,
               const float* __restrict__ b)
{
    __shared__ float ss[4], sqs[4];
    float* p = data + (size_t)blockIdx.x * HID;
    int t = threadIdx.x;

    float4 v = ((const float4*)p)[t];
    float s  = v.x + v.y + v.z + v.w;
    float sq = v.x * v.x + v.y * v.y + v.z * v.z + v.w * v.w;

#pragma unroll
    for (int o = 16; o > 0; o >>= 1) {
        s  += __shfl_xor_sync(0xffffffffu, s,  o);
        sq += __shfl_xor_sync(0xffffffffu, sq, o);
    }
    int warp = t >> 5;
    if ((t & 31) == 0) { ss[warp] = s; sqs[warp] = sq; }
    __syncthreads();
    s  = ss[0]  + ss[1]  + ss[2]  + ss[3];
    sq = sqs[0] + sqs[1] + sqs[2] + sqs[3];

    float mu  = s * (1.0f / HID);
    float var = sq * (1.0f / HID) - mu * mu;
    float inv = rsqrtf(var + LN_EPS);

    float4 wv = ((const float4*)w)[t];
    float4 bv = ((const float4*)b)[t];
    float4 o;
    o.x = (v.x - mu) * inv * wv.x + bv.x;
    o.y = (v.y - mu) * inv * wv.y + bv.y;
    o.z = (v.z - mu) * inv * wv.z + bv.z;
    o.w = (v.w - mu) * inv * wv.w + bv.w;
    ((float4*)p)[t] = o;
}

// ---------------------------------------------------------------------------
extern "C" void kernel_launch(void* const* d_in, const int* in_sizes, int n_in,
                              void* d_out, int out_size)
{
    const float* x     = (const float*)d_in[0];
    const float* hxs   = (const float*)d_in[1];
    const float* masks = (const float*)d_in[2];
    const float* W_ih  = (const float*)d_in[3];
    const float* W_hh  = (const float*)d_in[4];
    const float* b_ih  = (const float*)d_in[5];
    const float* b_hh  = (const float*)d_in[6];
    const float* ln_w  = (const float*)d_in[7];
    const float* ln_b  = (const float*)d_in[8];
    float* out = (float*)d_out;

    float *gi;
    __nv_bfloat16 *xh, *xl, *wih_h, *wih_l, *h0h, *h0l, *h1h, *h1l;
    unsigned* barp;
    cudaGetSymbolAddress((void**)&gi, g_gi);
    cudaGetSymbolAddress((void**)&xh, g_xh);
    cudaGetSymbolAddress((void**)&xl, g_xl);
    cudaGetSymbolAddress((void**)&wih_h, g_wih_h);
    cudaGetSymbolAddress((void**)&wih_l, g_wih_l);
    cudaGetSymbolAddress((void**)&h0h, g_h0h);
    cudaGetSymbolAddress((void**)&h0l, g_h0l);
    cudaGetSymbolAddress((void**)&h1h, g_h1h);
    cudaGetSymbolAddress((void**)&h1l, g_h1l);
    cudaGetSymbolAddress((void**)&barp, g_bar);

    // W_hh split target (device symbols used directly inside gru_scan)
    __nv_bfloat16 *whh_h, *whh_l;
    cudaGetSymbolAddress((void**)&whh_h, g_whh_h);
    cudaGetSymbolAddress((void**)&whh_l, g_whh_l);

    cudaMemsetAsync(barp, 0, sizeof(unsigned));

    // 0) One-time fp32 -> split-bf16 conversions.
    {
        int n4;
        n4 = T_STEPS * N_ENV * IN_D / 4;
        split_bf16<<<(n4 + 255) / 256, 256>>>(x, xh, xl, n4);
        n4 = G3 * IN_D / 4;
        split_bf16<<<(n4 + 255) / 256, 256>>>(W_ih, wih_h, wih_l, n4);
        n4 = G3 * HID / 4;
        split_bf16<<<(n4 + 255) / 256, 256>>>(W_hh, whh_h, whh_l, n4);
        n4 = N_ENV * HID / 4;
        split_bf16<<<(n4 + 255) / 256, 256>>>(hxs, h0h, h0l, n4);
    }

    // 1) GI = x @ W_ih^T + b_ih (tensor cores).
    {
        dim3 grid(G3 / 64, (T_STEPS * N_ENV) / 64);
        gemm_gi<<<grid, 128>>>(xh, xl, wih_h, wih_l, b_ih, gi, G3, IN_D);
    }

    // 2) Persistent fused scan (all 128 steps in one kernel).
    {
        size_t smem = (size_t)SMEM_ELEMS * sizeof(__nv_bfloat16);
        cudaFuncSetAttribute(gru_scan, cudaFuncAttributeMaxDynamicSharedMemorySize,
                             (int)smem);
        dim3 grid(HID / 32, N_ENV / 64);   // 16 x 8 = 128 CTAs
        gru_scan<<<grid, 256, smem>>>(gi, masks, hxs, b_hh, out,
                                      h0h, h0l, h1h, h1l);
    }

    // 3) h_last (raw) to tail before LN rewrites rows.
    copy_hlast<<<(N_ENV * HID / 4) / 256, 256>>>(
        out + (size_t)(T_STEPS - 1) * N_ENV * HID,
        out + (size_t)T_STEPS * N_ENV * HID);

    // 4) In-place LayerNorm over all T*N rows.
    layernorm_rows<<<T_STEPS * N_ENV, 128>>>(out, ln_w, ln_b);
}

// round 7
// speedup vs baseline: 3.4006x; 1.2352x over previous
#include <cuda_runtime.h>
#include <cuda_fp16.h>
#include <cstdint>
#include <math.h>

#define T_STEPS 128
#define N_ENV   512
#define IN_D    512
#define HID     512
#define G3      (3 * HID)      // 1536
#define LN_EPS  1e-5f
#define SCAN_CTAS 128

// ---------------------------------------------------------------------------
// Persistent scratch (static __device__ arrays).
// ---------------------------------------------------------------------------
__device__ float g_gi[(size_t)T_STEPS * N_ENV * G3];          // 402 MB
__device__ __half g_xf[(size_t)T_STEPS * N_ENV * IN_D];       // 67 MB (fp16 x)
__device__ __half g_wih_h[(size_t)G3 * IN_D];
__device__ __half g_wih_l[(size_t)G3 * IN_D];
__device__ __half g_whh_h[(size_t)G3 * HID];
__device__ __half g_whh_l[(size_t)G3 * HID];
__device__ __half g_h0[(size_t)N_ENV * HID];                  // ping-pong h
__device__ __half g_h1[(size_t)N_ENV * HID];
__device__ unsigned g_bar;

// ---------------------------------------------------------------------------
// fp32 -> fp16 (single) and fp32 -> (hi, lo) fp16 split.
// ---------------------------------------------------------------------------
__global__ void __launch_bounds__(256)
cvt_fp16(const float* __restrict__ src, __half* __restrict__ dst, int n4)
{
    int idx = blockIdx.x * 256 + threadIdx.x;
    if (idx >= n4) return;
    float4 v = ((const float4*)src)[idx];
    ((__half2*)dst)[2 * idx]     = __floats2half2_rn(v.x, v.y);
    ((__half2*)dst)[2 * idx + 1] = __floats2half2_rn(v.z, v.w);
}

__global__ void __launch_bounds__(256)
split_fp16(const float* __restrict__ src, __half* __restrict__ hi,
           __half* __restrict__ lo, int n4)
{
    int idx = blockIdx.x * 256 + threadIdx.x;
    if (idx >= n4) return;
    float4 v = ((const float4*)src)[idx];
    __half h0 = __float2half_rn(v.x);
    __half h1 = __float2half_rn(v.y);
    __half h2 = __float2half_rn(v.z);
    __half h3 = __float2half_rn(v.w);
    __half l0 = __float2half_rn(v.x - __half2float(h0));
    __half l1 = __float2half_rn(v.y - __half2float(h1));
    __half l2 = __float2half_rn(v.z - __half2float(h2));
    __half l3 = __float2half_rn(v.w - __half2float(h3));
    ((__half2*)hi)[2 * idx]     = __halves2half2(h0, h1);
    ((__half2*)hi)[2 * idx + 1] = __halves2half2(h2, h3);
    ((__half2*)lo)[2 * idx]     = __halves2half2(l0, l1);
    ((__half2*)lo)[2 * idx + 1] = __halves2half2(l2, l3);
}

// ---------------------------------------------------------------------------
// mma / ldmatrix primitives (fp16)
// ---------------------------------------------------------------------------
__device__ __forceinline__ void ldsm_x4(uint32_t& r0, uint32_t& r1,
                                        uint32_t& r2, uint32_t& r3,
                                        uint32_t addr)
{
    asm volatile("ldmatrix.sync.aligned.m8n8.x4.shared.b16 {%0,%1,%2,%3}, [%4];\n"
                 : "=r"(r0), "=r"(r1), "=r"(r2), "=r"(r3) : "r"(addr));
}

__device__ __forceinline__ void mma_fp16(float* c, const uint32_t* a,
                                         uint32_t b0, uint32_t b1)
{
    asm volatile("mma.sync.aligned.m16n8k16.row.col.f32.f16.f16.f32 "
                 "{%0,%1,%2,%3},{%4,%5,%6,%7},{%8,%9},{%0,%1,%2,%3};\n"
                 : "+f"(c[0]), "+f"(c[1]), "+f"(c[2]), "+f"(c[3])
                 : "r"(a[0]), "r"(a[1]), "r"(a[2]), "r"(a[3]), "r"(b0), "r"(b1));
}

// ===========================================================================
// GI GEMM: C[M,1536] = x_fp16 @ (Wh + Wl)^T + bias  (2-term fp16)
// CTA 64x64, 4 warps of 32x32, BK=64.
// ===========================================================================
#define SSTQ 72

__global__ void __launch_bounds__(128)
gemm_gi(const __half* __restrict__ A, const __half* __restrict__ Bh,
        const __half* __restrict__ Bl, const float* __restrict__ bias,
        float* __restrict__ C, int Nc, int K)
{
    __shared__ __half sA[64 * SSTQ];
    __shared__ __half sBh[64 * SSTQ], sBl[64 * SSTQ];

    const int tid  = threadIdx.x;
    const int w    = tid >> 5;
    const int lane = tid & 31;
    const int bm   = blockIdx.y * 64;
    const int bn   = blockIdx.x * 64;
    const int wm   = (w & 1) * 32;
    const int wn   = (w >> 1) * 32;

    float acc[2][4][4];
#pragma unroll
    for (int i = 0; i < 2; ++i)
#pragma unroll
        for (int j = 0; j < 4; ++j)
#pragma unroll
            for (int k = 0; k < 4; ++k) acc[i][j][k] = 0.0f;

    const uint32_t sAB  = (uint32_t)__cvta_generic_to_shared(sA);
    const uint32_t sBhB = (uint32_t)__cvta_generic_to_shared(sBh);
    const uint32_t sBlB = (uint32_t)__cvta_generic_to_shared(sBl);

    const int a_row = wm + (lane & 7) + ((lane >> 3) & 1) * 8;
    const int a_k   = (lane >> 4) << 3;
    const int b_row = wn + (lane & 7) + ((lane >> 4) << 3);
    const int b_k   = ((lane >> 3) & 1) << 3;

    for (int k0 = 0; k0 < K; k0 += 64) {
#pragma unroll
        for (int i = 0; i < 4; ++i) {
            int idx = tid + i * 128;
            int row = idx >> 3;
            int kc  = (idx & 7) << 3;
            size_t ga = (size_t)(bm + row) * K + k0 + kc;
            size_t gb = (size_t)(bn + row) * K + k0 + kc;
            int s = row * SSTQ + kc;
            uint4 va = *(const uint4*)(A + ga);
            *(uint2*)&sA[s]     = make_uint2(va.x, va.y);
            *(uint2*)&sA[s + 4] = make_uint2(va.z, va.w);
            uint4 wh = *(const uint4*)(Bh + gb);
            uint4 wl = *(const uint4*)(Bl + gb);
            *(uint2*)&sBh[s]     = make_uint2(wh.x, wh.y);
            *(uint2*)&sBh[s + 4] = make_uint2(wh.z, wh.w);
            *(uint2*)&sBl[s]     = make_uint2(wl.x, wl.y);
            *(uint2*)&sBl[s + 4] = make_uint2(wl.z, wl.w);
        }
        __syncthreads();

#pragma unroll
        for (int kk = 0; kk < 64; kk += 16) {
            const uint32_t mstep = 16 * SSTQ * 2;
            uint32_t aoff = (uint32_t)((a_row * SSTQ + kk + a_k) * 2);
            uint32_t boff = (uint32_t)((b_row * SSTQ + kk + b_k) * 2);

            uint32_t a0[4], a1[4];
            ldsm_x4(a0[0], a0[1], a0[2], a0[3], sAB + aoff);
            ldsm_x4(a1[0], a1[1], a1[2], a1[3], sAB + aoff + mstep);

            uint32_t bh0[4], bh1[4], bl0[4], bl1[4];
            ldsm_x4(bh0[0], bh0[1], bh0[2], bh0[3], sBhB + boff);
            ldsm_x4(bh1[0], bh1[1], bh1[2], bh1[3], sBhB + boff + mstep);
            ldsm_x4(bl0[0], bl0[1], bl0[2], bl0[3], sBlB + boff);
            ldsm_x4(bl1[0], bl1[1], bl1[2], bl1[3], sBlB + boff + mstep);

#pragma unroll
            for (int mt = 0; mt < 2; ++mt) {
                const uint32_t* aP = mt ? a1 : a0;
#pragma unroll
                for (int nt = 0; nt < 4; ++nt) {
                    const uint32_t* bH = (nt < 2) ? bh0 : bh1;
                    const uint32_t* bL = (nt < 2) ? bl0 : bl1;
                    int p = (nt & 1) * 2;
                    float* c = acc[mt][nt];
                    mma_fp16(c, aP, bH[p], bH[p + 1]);
                    mma_fp16(c, aP, bL[p], bL[p + 1]);
                }
            }
        }
        __syncthreads();
    }

#pragma unroll
    for (int mt = 0; mt < 2; ++mt) {
#pragma unroll
        for (int nt = 0; nt < 4; ++nt) {
            int r0 = bm + wm + mt * 16 + (lane >> 2);
            int cg = bn + wn + nt * 8 + ((lane & 3) << 1);
            float b0 = bias[cg], b1 = bias[cg + 1];
            float2 o0 = make_float2(acc[mt][nt][0] + b0, acc[mt][nt][1] + b1);
            float2 o1 = make_float2(acc[mt][nt][2] + b0, acc[mt][nt][3] + b1);
            *(float2*)(C + (size_t)r0 * Nc + cg)       = o0;
            *(float2*)(C + (size_t)(r0 + 8) * Nc + cg) = o1;
        }
    }
}

// ===========================================================================
// Persistent fused GRU scan (2-term fp16).
// Grid (16, 8) = 128 CTAs x 256 threads. W_hh slice (96 rows x 512, hi+lo)
// resident in smem; h single fp16 staged per 64-K chunk; gate fused.
// ===========================================================================
#define WSTR 520
#define HSTR 72
#define SM_WH 0
#define SM_WL (96 * WSTR)
#define SM_H  (2 * 96 * WSTR)
#define SMEM_ELEMS (2 * 96 * WSTR + 64 * HSTR)

__global__ void __launch_bounds__(256)
gru_scan(const float* __restrict__ gi_all, const float* __restrict__ masks,
         const float* __restrict__ hxs, const float* __restrict__ b_hh,
         float* __restrict__ out,
         __half* __restrict__ h0, __half* __restrict__ h1)
{
    extern __shared__ __half sm[];
    __half* sWh = sm + SM_WH;
    __half* sWl = sm + SM_WL;
    __half* sH  = sm + SM_H;

    const int tid  = threadIdx.x;
    const int w    = tid >> 5;
    const int lane = tid & 31;
    const int wq   = w >> 1;         // env group 0..3
    const int wr   = w & 1;          // col group 0..1
    const int c0   = blockIdx.x * 32;
    const int bm   = blockIdx.y * 64;

    const uint32_t sWhB = (uint32_t)__cvta_generic_to_shared(sWh);
    const uint32_t sWlB = (uint32_t)__cvta_generic_to_shared(sWl);
    const uint32_t sHB  = (uint32_t)__cvta_generic_to_shared(sH);

    // ---- stage W_hh slice once ----
    for (int i = tid; i < 96 * 64; i += 256) {
        int row = i >> 6;
        int seg = (i & 63) << 3;
        int ch  = row >> 5;
        int c   = row & 31;
        size_t g = (size_t)(ch * HID + c0 + c) * HID + seg;
        *(uint4*)&sWh[row * WSTR + seg] = *(const uint4*)&g_whh_h[g];
        *(uint4*)&sWl[row * WSTR + seg] = *(const uint4*)&g_whh_l[g];
    }

    const int env0 = bm + wq * 16 + (lane >> 2);
    const int env1 = env0 + 8;
    const int colbase = c0 + wr * 16;

    float bh[3][2][2], hprev[2][2][2];
#pragma unroll
    for (int ch = 0; ch < 3; ++ch)
#pragma unroll
        for (int nt = 0; nt < 2; ++nt) {
            int col = colbase + nt * 8 + ((lane & 3) << 1);
            bh[ch][nt][0] = b_hh[ch * HID + col];
            bh[ch][nt][1] = b_hh[ch * HID + col + 1];
        }
#pragma unroll
    for (int e = 0; e < 2; ++e)
#pragma unroll
        for (int nt = 0; nt < 2; ++nt) {
            int env = e ? env1 : env0;
            int col = colbase + nt * 8 + ((lane & 3) << 1);
            float2 v = *(const float2*)&hxs[(size_t)env * HID + col];
            hprev[e][nt][0] = v.x; hprev[e][nt][1] = v.y;
        }

    const int a_row = wq * 16 + (lane & 7) + (((lane >> 3) & 1) << 3);
    const int a_k   = (lane >> 4) << 3;
    const int b_rowL = wr * 16 + (lane & 7) + ((lane >> 4) << 3);
    const int b_k   = ((lane >> 3) & 1) << 3;

    const int st_row = tid >> 2;
    const int st_seg = (tid & 3) << 4;

    __syncthreads();

    for (int t = 0; t < T_STEPS; ++t) {
        const __half* Rd = (t & 1) ? h1 : h0;
        __half* Wr = (t & 1) ? h0 : h1;
        const float* mrow = masks + (size_t)t * N_ENV;

        float m_st = mrow[bm + st_row];
        float m_e0 = mrow[env0];
        float m_e1 = mrow[env1];

        float acc[3][2][4];
#pragma unroll
        for (int ch = 0; ch < 3; ++ch)
#pragma unroll
            for (int nt = 0; nt < 2; ++nt)
#pragma unroll
                for (int j = 0; j < 4; ++j) acc[ch][nt][j] = 0.0f;

        for (int k0 = 0; k0 < HID; k0 += 64) {
            {
                size_t g = (size_t)(bm + st_row) * HID + k0 + st_seg;
                uint4 v0 = *(const uint4*)&Rd[g];
                uint4 v1 = *(const uint4*)&Rd[g + 8];
                if (m_st == 0.0f) { v0 = make_uint4(0,0,0,0); v1 = v0; }
                int s = st_row * HSTR + st_seg;
                *(uint4*)&sH[s]     = v0;
                *(uint4*)&sH[s + 8] = v1;
            }
            __syncthreads();

#pragma unroll
            for (int kk = 0; kk < 64; kk += 16) {
                uint32_t aoff = (uint32_t)((a_row * HSTR + kk + a_k) * 2);
                uint32_t ah[4];
                ldsm_x4(ah[0], ah[1], ah[2], ah[3], sHB + aoff);

#pragma unroll
                for (int ch = 0; ch < 3; ++ch) {
                    uint32_t boff = (uint32_t)(((ch * 32 + b_rowL) * WSTR
                                               + k0 + kk + b_k) * 2);
                    uint32_t bhk[4], blk[4];
                    ldsm_x4(bhk[0], bhk[1], bhk[2], bhk[3], sWhB + boff);
                    ldsm_x4(blk[0], blk[1], blk[2], blk[3], sWlB + boff);
#pragma unroll
                    for (int nt = 0; nt < 2; ++nt) {
                        int p = nt * 2;
                        float* c = acc[ch][nt];
                        mma_fp16(c, ah, bhk[p], bhk[p + 1]);
                        mma_fp16(c, ah, blk[p], blk[p + 1]);
                    }
                }
            }
            __syncthreads();
        }

        // ---- fused gate ----
        const float* gip = gi_all + (size_t)t * N_ENV * G3;
#pragma unroll
        for (int e = 0; e < 2; ++e) {
            int env = e ? env1 : env0;
            float m = e ? m_e1 : m_e0;
#pragma unroll
            for (int nt = 0; nt < 2; ++nt) {
                int col = colbase + nt * 8 + ((lane & 3) << 1);
                size_t gb = (size_t)env * G3 + col;
                float2 gr = *(const float2*)&gip[gb];
                float2 gz = *(const float2*)&gip[gb + HID];
                float2 gn = *(const float2*)&gip[gb + 2 * HID];
                int j0 = 2 * e;

                float hr0 = acc[0][nt][j0]     + bh[0][nt][0];
                float hr1 = acc[0][nt][j0 + 1] + bh[0][nt][1];
                float hz0 = acc[1][nt][j0]     + bh[1][nt][0];
                float hz1 = acc[1][nt][j0 + 1] + bh[1][nt][1];
                float hn0 = acc[2][nt][j0]     + bh[2][nt][0];
                float hn1 = acc[2][nt][j0 + 1] + bh[2][nt][1];

                float r0 = 1.0f / (1.0f + __expf(-(gr.x + hr0)));
                float r1 = 1.0f / (1.0f + __expf(-(gr.y + hr1)));
                float z0 = 1.0f / (1.0f + __expf(-(gz.x + hz0)));
                float z1 = 1.0f / (1.0f + __expf(-(gz.y + hz1)));
                float n0 = tanhf(gn.x + r0 * hn0);
                float n1 = tanhf(gn.y + r1 * hn1);

                float h0v = hprev[e][nt][0] * m;
                float h1v = hprev[e][nt][1] * m;
                float hw0 = (1.0f - z0) * n0 + z0 * h0v;
                float hw1 = (1.0f - z1) * n1 + z1 * h1v;
                hprev[e][nt][0] = hw0;
                hprev[e][nt][1] = hw1;

                *(float2*)&out[(size_t)t * N_ENV * HID + (size_t)env * HID + col]
                    = make_float2(hw0, hw1);
                *(__half2*)&Wr[(size_t)env * HID + col]
                    = __floats2half2_rn(hw0, hw1);
            }
        }

        // ---- grid barrier ----
        if (t < T_STEPS - 1) {
            __threadfence();
            __syncthreads();
            if (tid == 0) {
                atomicAdd(&g_bar, 1u);
                unsigned target = (unsigned)SCAN_CTAS * (unsigned)(t + 1);
                while (*(volatile unsigned*)&g_bar < target) { }
            }
            __syncthreads();
            __threadfence();
        }
    }
}

// ---------------------------------------------------------------------------
__global__ void __launch_bounds__(256)
copy_hlast(const float* __restrict__ src, float* __restrict__ dst)
{
    int idx = blockIdx.x * 256 + threadIdx.x;
    ((float4*)dst)[idx] = ((const float4*)src)[idx];
}

// ---------------------------------------------------------------------------
__global__ void __launch_bounds__(128)
layernorm_rows(float* __restrict__ data, const float* __restrict__ w,
               const float* __restrict__ b)
{
    __shared__ float ss[4], sqs[4];
    float* p = data + (size_t)blockIdx.x * HID;
    int t = threadIdx.x;

    float4 v = ((const float4*)p)[t];
    float s  = v.x + v.y + v.z + v.w;
    float sq = v.x * v.x + v.y * v.y + v.z * v.z + v.w * v.w;

#pragma unroll
    for (int o = 16; o > 0; o >>= 1) {
        s  += __shfl_xor_sync(0xffffffffu, s,  o);
        sq += __shfl_xor_sync(0xffffffffu, sq, o);
    }
    int warp = t >> 5;
    if ((t & 31) == 0) { ss[warp] = s; sqs[warp] = sq; }
    __syncthreads();
    s  = ss[0]  + ss[1]  + ss[2]  + ss[3];
    sq = sqs[0] + sqs[1] + sqs[2] + sqs[3];

    float mu  = s * (1.0f / HID);
    float var = sq * (1.0f / HID) - mu * mu;
    float inv = rsqrtf(var + LN_EPS);

    float4 wv = ((const float4*)w)[t];
    float4 bv = ((const float4*)b)[t];
    float4 o;
    o.x = (v.x - mu) * inv * wv.x + bv.x;
    o.y = (v.y - mu) * inv * wv.y + bv.y;
    o.z = (v.z - mu) * inv * wv.z + bv.z;
    o.w = (v.w - mu) * inv * wv.w + bv.w;
    ((float4*)p)[t] = o;
}

// ---------------------------------------------------------------------------
extern "C" void kernel_launch(void* const* d_in, const int* in_sizes, int n_in,
                              void* d_out, int out_size)
{
    const float* x     = (const float*)d_in[0];
    const float* hxs   = (const float*)d_in[1];
    const float* masks = (const float*)d_in[2];
    const float* W_ih  = (const float*)d_in[3];
    const float* W_hh  = (const float*)d_in[4];
    const float* b_ih  = (const float*)d_in[5];
    const float* b_hh  = (const float*)d_in[6];
    const float* ln_w  = (const float*)d_in[7];
    const float* ln_b  = (const float*)d_in[8];
    float* out = (float*)d_out;

    float* gi;
    __half *xf, *wih_h, *wih_l, *whh_h, *whh_l, *h0, *h1;
    unsigned* barp;
    cudaGetSymbolAddress((void**)&gi, g_gi);
    cudaGetSymbolAddress((void**)&xf, g_xf);
    cudaGetSymbolAddress((void**)&wih_h, g_wih_h);
    cudaGetSymbolAddress((void**)&wih_l, g_wih_l);
    cudaGetSymbolAddress((void**)&whh_h, g_whh_h);
    cudaGetSymbolAddress((void**)&whh_l, g_whh_l);
    cudaGetSymbolAddress((void**)&h0, g_h0);
    cudaGetSymbolAddress((void**)&h1, g_h1);
    cudaGetSymbolAddress((void**)&barp, g_bar);

    cudaMemsetAsync(barp, 0, sizeof(unsigned));

    // 0) One-time conversions.
    {
        int n4;
        n4 = T_STEPS * N_ENV * IN_D / 4;
        cvt_fp16<<<(n4 + 255) / 256, 256>>>(x, xf, n4);
        n4 = G3 * IN_D / 4;
        split_fp16<<<(n4 + 255) / 256, 256>>>(W_ih, wih_h, wih_l, n4);
        n4 = G3 * HID / 4;
        split_fp16<<<(n4 + 255) / 256, 256>>>(W_hh, whh_h, whh_l, n4);
        n4 = N_ENV * HID / 4;
        cvt_fp16<<<(n4 + 255) / 256, 256>>>(hxs, h0, n4);
    }

    // 1) GI = x @ W_ih^T + b_ih (2-term fp16).
    {
        dim3 grid(G3 / 64, (T_STEPS * N_ENV) / 64);
        gemm_gi<<<grid, 128>>>(xf, wih_h, wih_l, b_ih, gi, G3, IN_D);
    }

    // 2) Persistent fused scan.
    {
        size_t smem = (size_t)SMEM_ELEMS * sizeof(__half);
        cudaFuncSetAttribute(gru_scan, cudaFuncAttributeMaxDynamicSharedMemorySize,
                             (int)smem);
        dim3 grid(HID / 32, N_ENV / 64);   // 16 x 8 = 128 CTAs
        gru_scan<<<grid, 256, smem>>>(gi, masks, hxs, b_hh, out, h0, h1);
    }

    // 3) h_last (raw) to tail before LN rewrites rows.
    copy_hlast<<<(N_ENV * HID / 4) / 256, 256>>>(
        out + (size_t)(T_STEPS - 1) * N_ENV * HID,
        out + (size_t)T_STEPS * N_ENV * HID);

    // 4) In-place LayerNorm over all T*N rows.
    layernorm_rows<<<T_STEPS * N_ENV, 128>>>(out, ln_w, ln_b);
}

// round 8
// speedup vs baseline: 3.8894x; 1.1437x over previous
#include <cuda_runtime.h>
#include <cuda_fp16.h>
#include <cstdint>
#include <math.h>

#define T_STEPS 128
#define N_ENV   512
#define IN_D    512
#define HID     512
#define G3      (3 * HID)      // 1536
#define LN_EPS  1e-5f
#define SCAN_CTAS 128

// ---------------------------------------------------------------------------
// Persistent scratch.
// ---------------------------------------------------------------------------
__device__ float g_gi[(size_t)T_STEPS * N_ENV * G3];          // 402 MB
__device__ __half g_xf[(size_t)T_STEPS * N_ENV * IN_D];       // 67 MB
__device__ __half g_wih_h[(size_t)G3 * IN_D];
__device__ __half g_wih_l[(size_t)G3 * IN_D];
__device__ __half g_whh_h[(size_t)G3 * HID];
__device__ __half g_whh_l[(size_t)G3 * HID];
__device__ __half g_h0[(size_t)N_ENV * HID];                  // ping-pong h
__device__ __half g_h1[(size_t)N_ENV * HID];
__device__ unsigned g_bar;

// ---------------------------------------------------------------------------
__global__ void __launch_bounds__(256)
cvt_fp16(const float* __restrict__ src, __half* __restrict__ dst, int n4)
{
    int idx = blockIdx.x * 256 + threadIdx.x;
    if (idx >= n4) return;
    float4 v = ((const float4*)src)[idx];
    ((__half2*)dst)[2 * idx]     = __floats2half2_rn(v.x, v.y);
    ((__half2*)dst)[2 * idx + 1] = __floats2half2_rn(v.z, v.w);
}

__global__ void __launch_bounds__(256)
split_fp16(const float* __restrict__ src, __half* __restrict__ hi,
           __half* __restrict__ lo, int n4)
{
    int idx = blockIdx.x * 256 + threadIdx.x;
    if (idx >= n4) return;
    float4 v = ((const float4*)src)[idx];
    __half h0 = __float2half_rn(v.x);
    __half h1 = __float2half_rn(v.y);
    __half h2 = __float2half_rn(v.z);
    __half h3 = __float2half_rn(v.w);
    __half l0 = __float2half_rn(v.x - __half2float(h0));
    __half l1 = __float2half_rn(v.y - __half2float(h1));
    __half l2 = __float2half_rn(v.z - __half2float(h2));
    __half l3 = __float2half_rn(v.w - __half2float(h3));
    ((__half2*)hi)[2 * idx]     = __halves2half2(h0, h1);
    ((__half2*)hi)[2 * idx + 1] = __halves2half2(h2, h3);
    ((__half2*)lo)[2 * idx]     = __halves2half2(l0, l1);
    ((__half2*)lo)[2 * idx + 1] = __halves2half2(l2, l3);
}

// ---------------------------------------------------------------------------
__device__ __forceinline__ void ldsm_x4(uint32_t& r0, uint32_t& r1,
                                        uint32_t& r2, uint32_t& r3,
                                        uint32_t addr)
{
    asm volatile("ldmatrix.sync.aligned.m8n8.x4.shared.b16 {%0,%1,%2,%3}, [%4];\n"
                 : "=r"(r0), "=r"(r1), "=r"(r2), "=r"(r3) : "r"(addr));
}

// fp16 inputs, fp32 accumulate (hi term)
__device__ __forceinline__ void mma_f32(float* c, const uint32_t* a,
                                        uint32_t b0, uint32_t b1)
{
    asm volatile("mma.sync.aligned.m16n8k16.row.col.f32.f16.f16.f32 "
                 "{%0,%1,%2,%3},{%4,%5,%6,%7},{%8,%9},{%0,%1,%2,%3};\n"
                 : "+f"(c[0]), "+f"(c[1]), "+f"(c[2]), "+f"(c[3])
                 : "r"(a[0]), "r"(a[1]), "r"(a[2]), "r"(a[3]), "r"(b0), "r"(b1));
}

// fp16 inputs, fp16 accumulate (lo term; values ~1e-3, error negligible)
__device__ __forceinline__ void mma_f16(uint32_t* c, const uint32_t* a,
                                        uint32_t b0, uint32_t b1)
{
    asm volatile("mma.sync.aligned.m16n8k16.row.col.f16.f16.f16.f16 "
                 "{%0,%1},{%2,%3,%4,%5},{%6,%7},{%0,%1};\n"
                 : "+r"(c[0]), "+r"(c[1])
                 : "r"(a[0]), "r"(a[1]), "r"(a[2]), "r"(a[3]), "r"(b0), "r"(b1));
}

// ===========================================================================
// GI GEMM: C[M,1536] = x_fp16 @ (Wh + Wl)^T + bias
// CTA tile 128x64 (256 threads, 8 warps 4x2, warp tile 32x32), BK=64.
// Hi term -> f32 accum, lo term -> f16 accum.
// ===========================================================================
#define SSTQ 72

__global__ void __launch_bounds__(256)
gemm_gi(const __half* __restrict__ A, const __half* __restrict__ Bh,
        const __half* __restrict__ Bl, const float* __restrict__ bias,
        float* __restrict__ C, int Nc, int K)
{
    __shared__ __half sA[128 * SSTQ];
    __shared__ __half sBh[64 * SSTQ], sBl[64 * SSTQ];

    const int tid  = threadIdx.x;
    const int w    = tid >> 5;
    const int lane = tid & 31;
    const int bm   = blockIdx.y * 128;
    const int bn   = blockIdx.x * 64;
    const int wm   = (w & 3) * 32;
    const int wn   = (w >> 2) * 32;

    float acc[2][4][4];
    uint32_t accL[2][4][2];
#pragma unroll
    for (int i = 0; i < 2; ++i)
#pragma unroll
        for (int j = 0; j < 4; ++j) {
#pragma unroll
            for (int k = 0; k < 4; ++k) acc[i][j][k] = 0.0f;
            accL[i][j][0] = 0u; accL[i][j][1] = 0u;
        }

    const uint32_t sAB  = (uint32_t)__cvta_generic_to_shared(sA);
    const uint32_t sBhB = (uint32_t)__cvta_generic_to_shared(sBh);
    const uint32_t sBlB = (uint32_t)__cvta_generic_to_shared(sBl);

    const int a_row = wm + (lane & 7) + ((lane >> 3) & 1) * 8;
    const int a_k   = (lane >> 4) << 3;
    const int b_row = wn + (lane & 7) + ((lane >> 4) << 3);
    const int b_k   = ((lane >> 3) & 1) << 3;

    for (int k0 = 0; k0 < K; k0 += 64) {
        // stage A: 128 rows x 64 k
#pragma unroll
        for (int i = 0; i < 4; ++i) {
            int idx = tid + i * 256;
            int row = idx >> 3;
            int kc  = (idx & 7) << 3;
            size_t ga = (size_t)(bm + row) * K + k0 + kc;
            int s = row * SSTQ + kc;
            uint4 va = *(const uint4*)(A + ga);
            *(uint2*)&sA[s]     = make_uint2(va.x, va.y);
            *(uint2*)&sA[s + 4] = make_uint2(va.z, va.w);
        }
        // stage B: 64 rows x 64 k (hi + lo)
#pragma unroll
        for (int i = 0; i < 2; ++i) {
            int idx = tid + i * 256;
            int row = idx >> 3;
            int kc  = (idx & 7) << 3;
            size_t gb = (size_t)(bn + row) * K + k0 + kc;
            int s = row * SSTQ + kc;
            uint4 wh = *(const uint4*)(Bh + gb);
            uint4 wl = *(const uint4*)(Bl + gb);
            *(uint2*)&sBh[s]     = make_uint2(wh.x, wh.y);
            *(uint2*)&sBh[s + 4] = make_uint2(wh.z, wh.w);
            *(uint2*)&sBl[s]     = make_uint2(wl.x, wl.y);
            *(uint2*)&sBl[s + 4] = make_uint2(wl.z, wl.w);
        }
        __syncthreads();

#pragma unroll
        for (int kk = 0; kk < 64; kk += 16) {
            const uint32_t mstep = 16 * SSTQ * 2;
            uint32_t aoff = (uint32_t)((a_row * SSTQ + kk + a_k) * 2);
            uint32_t boff = (uint32_t)((b_row * SSTQ + kk + b_k) * 2);

            uint32_t a0[4], a1[4];
            ldsm_x4(a0[0], a0[1], a0[2], a0[3], sAB + aoff);
            ldsm_x4(a1[0], a1[1], a1[2], a1[3], sAB + aoff + mstep);

            uint32_t bh0[4], bh1[4], bl0[4], bl1[4];
            ldsm_x4(bh0[0], bh0[1], bh0[2], bh0[3], sBhB + boff);
            ldsm_x4(bh1[0], bh1[1], bh1[2], bh1[3], sBhB + boff + mstep);
            ldsm_x4(bl0[0], bl0[1], bl0[2], bl0[3], sBlB + boff);
            ldsm_x4(bl1[0], bl1[1], bl1[2], bl1[3], sBlB + boff + mstep);

#pragma unroll
            for (int mt = 0; mt < 2; ++mt) {
                const uint32_t* aP = mt ? a1 : a0;
#pragma unroll
                for (int nt = 0; nt < 4; ++nt) {
                    const uint32_t* bH = (nt < 2) ? bh0 : bh1;
                    const uint32_t* bL = (nt < 2) ? bl0 : bl1;
                    int p = (nt & 1) * 2;
                    mma_f32(acc[mt][nt], aP, bH[p], bH[p + 1]);
                    mma_f16(accL[mt][nt], aP, bL[p], bL[p + 1]);
                }
            }
        }
        __syncthreads();
    }

#pragma unroll
    for (int mt = 0; mt < 2; ++mt) {
#pragma unroll
        for (int nt = 0; nt < 4; ++nt) {
            int r0 = bm + wm + mt * 16 + (lane >> 2);
            int cg = bn + wn + nt * 8 + ((lane & 3) << 1);
            float b0 = bias[cg], b1 = bias[cg + 1];
            float2 l01 = __half22float2(*(__half2*)&accL[mt][nt][0]);
            float2 l23 = __half22float2(*(__half2*)&accL[mt][nt][1]);
            float2 o0 = make_float2(acc[mt][nt][0] + l01.x + b0,
                                    acc[mt][nt][1] + l01.y + b1);
            float2 o1 = make_float2(acc[mt][nt][2] + l23.x + b0,
                                    acc[mt][nt][3] + l23.y + b1);
            *(float2*)(C + (size_t)r0 * Nc + cg)       = o0;
            *(float2*)(C + (size_t)(r0 + 8) * Nc + cg) = o1;
        }
    }
}

// ===========================================================================
// Persistent fused GRU scan. Grid (16, 8) = 128 CTAs x 256 threads.
// K-chunks of 128 (4/step), register-pipelined h staging, gi prefetch,
// hi term f32 accum + lo term f16 accum.
// ===========================================================================
#define WSTR 520
#define HSTR 136
#define SM_WH 0
#define SM_WL (96 * WSTR)
#define SM_H  (2 * 96 * WSTR)
#define SMEM_ELEMS (2 * 96 * WSTR + 64 * HSTR)   // 108544 halves = 212 KB

__global__ void __launch_bounds__(256)
gru_scan(const float* __restrict__ gi_all, const float* __restrict__ masks,
         const float* __restrict__ hxs, const float* __restrict__ b_hh,
         float* __restrict__ out,
         __half* __restrict__ h0, __half* __restrict__ h1)
{
    extern __shared__ __half sm[];
    __half* sWh = sm + SM_WH;
    __half* sWl = sm + SM_WL;
    __half* sH  = sm + SM_H;

    const int tid  = threadIdx.x;
    const int w    = tid >> 5;
    const int lane = tid & 31;
    const int wq   = w >> 1;
    const int wr   = w & 1;
    const int c0   = blockIdx.x * 32;
    const int bm   = blockIdx.y * 64;

    const uint32_t sWhB = (uint32_t)__cvta_generic_to_shared(sWh);
    const uint32_t sWlB = (uint32_t)__cvta_generic_to_shared(sWl);
    const uint32_t sHB  = (uint32_t)__cvta_generic_to_shared(sH);

    // ---- stage W_hh slice once ----
    for (int i = tid; i < 96 * 64; i += 256) {
        int row = i >> 6;
        int seg = (i & 63) << 3;
        int ch  = row >> 5;
        int c   = row & 31;
        size_t g = (size_t)(ch * HID + c0 + c) * HID + seg;
        *(uint4*)&sWh[row * WSTR + seg] = *(const uint4*)&g_whh_h[g];
        *(uint4*)&sWl[row * WSTR + seg] = *(const uint4*)&g_whh_l[g];
    }

    const int env0 = bm + wq * 16 + (lane >> 2);
    const int env1 = env0 + 8;
    const int colbase = c0 + wr * 16;

    float bh[3][2][2], hprev[2][2][2];
#pragma unroll
    for (int ch = 0; ch < 3; ++ch)
#pragma unroll
        for (int nt = 0; nt < 2; ++nt) {
            int col = colbase + nt * 8 + ((lane & 3) << 1);
            bh[ch][nt][0] = b_hh[ch * HID + col];
            bh[ch][nt][1] = b_hh[ch * HID + col + 1];
        }
#pragma unroll
    for (int e = 0; e < 2; ++e)
#pragma unroll
        for (int nt = 0; nt < 2; ++nt) {
            int env = e ? env1 : env0;
            int col = colbase + nt * 8 + ((lane & 3) << 1);
            float2 v = *(const float2*)&hxs[(size_t)env * HID + col];
            hprev[e][nt][0] = v.x; hprev[e][nt][1] = v.y;
        }

    const int a_row = wq * 16 + (lane & 7) + (((lane >> 3) & 1) << 3);
    const int a_k   = (lane >> 4) << 3;
    const int b_rowL = wr * 16 + (lane & 7) + ((lane >> 4) << 3);
    const int b_k   = ((lane >> 3) & 1) << 3;

    const int st_row = tid >> 2;           // 0..63
    const int st_seg = (tid & 3) << 5;     // 0,32,64,96 halves (64B each)

    __syncthreads();

    for (int t = 0; t < T_STEPS; ++t) {
        const __half* Rd = (t & 1) ? h1 : h0;
        __half* Wr = (t & 1) ? h0 : h1;
        const float* mrow = masks + (size_t)t * N_ENV;

        float m_st = mrow[bm + st_row];
        float m_e0 = mrow[env0];
        float m_e1 = mrow[env1];

        // ---- prefetch gate inputs early (hidden behind mma) ----
        float grv[2][2][2], gzv[2][2][2], gnv[2][2][2];
        {
            const float* gip = gi_all + (size_t)t * N_ENV * G3;
#pragma unroll
            for (int e = 0; e < 2; ++e) {
                int env = e ? env1 : env0;
#pragma unroll
                for (int nt = 0; nt < 2; ++nt) {
                    int col = colbase + nt * 8 + ((lane & 3) << 1);
                    size_t gb = (size_t)env * G3 + col;
                    float2 a = *(const float2*)&gip[gb];
                    float2 b = *(const float2*)&gip[gb + HID];
                    float2 c = *(const float2*)&gip[gb + 2 * HID];
                    grv[e][nt][0] = a.x; grv[e][nt][1] = a.y;
                    gzv[e][nt][0] = b.x; gzv[e][nt][1] = b.y;
                    gnv[e][nt][0] = c.x; gnv[e][nt][1] = c.y;
                }
            }
        }

        float acc[3][2][4];
        uint32_t accL[3][2][2];
#pragma unroll
        for (int ch = 0; ch < 3; ++ch)
#pragma unroll
            for (int nt = 0; nt < 2; ++nt) {
#pragma unroll
                for (int j = 0; j < 4; ++j) acc[ch][nt][j] = 0.0f;
                accL[ch][nt][0] = 0u; accL[ch][nt][1] = 0u;
            }

        // preload chunk 0 h into registers
        uint4 pv[4], nv[4];
        {
            size_t g = (size_t)(bm + st_row) * HID + st_seg;
#pragma unroll
            for (int j = 0; j < 4; ++j) pv[j] = *(const uint4*)&Rd[g + j * 8];
        }

        for (int cnk = 0; cnk < 4; ++cnk) {
            __syncthreads();   // previous chunk's mma done reading sH
            {
                uint4 z = make_uint4(0, 0, 0, 0);
                int s = st_row * HSTR + st_seg;
#pragma unroll
                for (int j = 0; j < 4; ++j)
                    *(uint4*)&sH[s + j * 8] = (m_st == 0.0f) ? z : pv[j];
            }
            if (cnk < 3) {
                size_t g = (size_t)(bm + st_row) * HID + (cnk + 1) * 128 + st_seg;
#pragma unroll
                for (int j = 0; j < 4; ++j) nv[j] = *(const uint4*)&Rd[g + j * 8];
            }
            __syncthreads();

            const int k0 = cnk * 128;
#pragma unroll
            for (int kk = 0; kk < 128; kk += 16) {
                uint32_t aoff = (uint32_t)((a_row * HSTR + kk + a_k) * 2);
                uint32_t ah[4];
                ldsm_x4(ah[0], ah[1], ah[2], ah[3], sHB + aoff);

#pragma unroll
                for (int ch = 0; ch < 3; ++ch) {
                    uint32_t boff = (uint32_t)(((ch * 32 + b_rowL) * WSTR
                                               + k0 + kk + b_k) * 2);
                    uint32_t bhk[4], blk[4];
                    ldsm_x4(bhk[0], bhk[1], bhk[2], bhk[3], sWhB + boff);
                    ldsm_x4(blk[0], blk[1], blk[2], blk[3], sWlB + boff);
#pragma unroll
                    for (int nt = 0; nt < 2; ++nt) {
                        int p = nt * 2;
                        mma_f32(acc[ch][nt], ah, bhk[p], bhk[p + 1]);
                        mma_f16(accL[ch][nt], ah, blk[p], blk[p + 1]);
                    }
                }
            }
#pragma unroll
            for (int j = 0; j < 4; ++j) pv[j] = nv[j];
        }

        // ---- fused gate ----
#pragma unroll
        for (int e = 0; e < 2; ++e) {
            int env = e ? env1 : env0;
            float m = e ? m_e1 : m_e0;
#pragma unroll
            for (int nt = 0; nt < 2; ++nt) {
                int col = colbase + nt * 8 + ((lane & 3) << 1);
                int j0 = 2 * e;
                float2 lr = __half22float2(*(__half2*)&accL[0][nt][e]);
                float2 lz = __half22float2(*(__half2*)&accL[1][nt][e]);
                float2 ln = __half22float2(*(__half2*)&accL[2][nt][e]);

                float hr0 = acc[0][nt][j0]     + lr.x + bh[0][nt][0];
                float hr1 = acc[0][nt][j0 + 1] + lr.y + bh[0][nt][1];
                float hz0 = acc[1][nt][j0]     + lz.x + bh[1][nt][0];
                float hz1 = acc[1][nt][j0 + 1] + lz.y + bh[1][nt][1];
                float hn0 = acc[2][nt][j0]     + ln.x + bh[2][nt][0];
                float hn1 = acc[2][nt][j0 + 1] + ln.y + bh[2][nt][1];

                float r0 = 1.0f / (1.0f + __expf(-(grv[e][nt][0] + hr0)));
                float r1 = 1.0f / (1.0f + __expf(-(grv[e][nt][1] + hr1)));
                float z0 = 1.0f / (1.0f + __expf(-(gzv[e][nt][0] + hz0)));
                float z1 = 1.0f / (1.0f + __expf(-(gzv[e][nt][1] + hz1)));
                float n0 = tanhf(gnv[e][nt][0] + r0 * hn0);
                float n1 = tanhf(gnv[e][nt][1] + r1 * hn1);

                float h0v = hprev[e][nt][0] * m;
                float h1v = hprev[e][nt][1] * m;
                float hw0 = (1.0f - z0) * n0 + z0 * h0v;
                float hw1 = (1.0f - z1) * n1 + z1 * h1v;
                hprev[e][nt][0] = hw0;
                hprev[e][nt][1] = hw1;

                *(float2*)&out[(size_t)t * N_ENV * HID + (size_t)env * HID + col]
                    = make_float2(hw0, hw1);
                *(__half2*)&Wr[(size_t)env * HID + col]
                    = __floats2half2_rn(hw0, hw1);
            }
        }

        // ---- grid barrier ----
        if (t < T_STEPS - 1) {
            __threadfence();
            __syncthreads();
            if (tid == 0) {
                atomicAdd(&g_bar, 1u);
                unsigned target = (unsigned)SCAN_CTAS * (unsigned)(t + 1);
                while (*(volatile unsigned*)&g_bar < target) { }
            }
            __syncthreads();
            __threadfence();
        }
    }
}

// ---------------------------------------------------------------------------
__global__ void __launch_bounds__(256)
copy_hlast(const float* __restrict__ src, float* __restrict__ dst)
{
    int idx = blockIdx.x * 256 + threadIdx.x;
    ((float4*)dst)[idx] = ((const float4*)src)[idx];
}

// ---------------------------------------------------------------------------
__global__ void __launch_bounds__(128)
layernorm_rows(float* __restrict__ data, const float* __restrict__ w,
               const float* __restrict__ b)
{
    __shared__ float ss[4], sqs[4];
    float* p = data + (size_t)blockIdx.x * HID;
    int t = threadIdx.x;

    float4 v = ((const float4*)p)[t];
    float s  = v.x + v.y + v.z + v.w;
    float sq = v.x * v.x + v.y * v.y + v.z * v.z + v.w * v.w;

#pragma unroll
    for (int o = 16; o > 0; o >>= 1) {
        s  += __shfl_xor_sync(0xffffffffu, s,  o);
        sq += __shfl_xor_sync(0xffffffffu, sq, o);
    }
    int warp = t >> 5;
    if ((t & 31) == 0) { ss[warp] = s; sqs[warp] = sq; }
    __syncthreads();
    s  = ss[0]  + ss[1]  + ss[2]  + ss[3];
    sq = sqs[0] + sqs[1] + sqs[2] + sqs[3];

    float mu  = s * (1.0f / HID);
    float var = sq * (1.0f / HID) - mu * mu;
    float inv = rsqrtf(var + LN_EPS);

    float4 wv = ((const float4*)w)[t];
    float4 bv = ((const float4*)b)[t];
    float4 o;
    o.x = (v.x - mu) * inv * wv.x + bv.x;
    o.y = (v.y - mu) * inv * wv.y + bv.y;
    o.z = (v.z - mu) * inv * wv.z + bv.z;
    o.w = (v.w - mu) * inv * wv.w + bv.w;
    ((float4*)p)[t] = o;
}

// ---------------------------------------------------------------------------
extern "C" void kernel_launch(void* const* d_in, const int* in_sizes, int n_in,
                              void* d_out, int out_size)
{
    const float* x     = (const float*)d_in[0];
    const float* hxs   = (const float*)d_in[1];
    const float* masks = (const float*)d_in[2];
    const float* W_ih  = (const float*)d_in[3];
    const float* W_hh  = (const float*)d_in[4];
    const float* b_ih  = (const float*)d_in[5];
    const float* b_hh  = (const float*)d_in[6];
    const float* ln_w  = (const float*)d_in[7];
    const float* ln_b  = (const float*)d_in[8];
    float* out = (float*)d_out;

    float* gi;
    __half *xf, *wih_h, *wih_l, *whh_h, *whh_l, *h0, *h1;
    unsigned* barp;
    cudaGetSymbolAddress((void**)&gi, g_gi);
    cudaGetSymbolAddress((void**)&xf, g_xf);
    cudaGetSymbolAddress((void**)&wih_h, g_wih_h);
    cudaGetSymbolAddress((void**)&wih_l, g_wih_l);
    cudaGetSymbolAddress((void**)&whh_h, g_whh_h);
    cudaGetSymbolAddress((void**)&whh_l, g_whh_l);
    cudaGetSymbolAddress((void**)&h0, g_h0);
    cudaGetSymbolAddress((void**)&h1, g_h1);
    cudaGetSymbolAddress((void**)&barp, g_bar);

    cudaMemsetAsync(barp, 0, sizeof(unsigned));

    // 0) One-time conversions.
    {
        int n4;
        n4 = T_STEPS * N_ENV * IN_D / 4;
        cvt_fp16<<<(n4 + 255) / 256, 256>>>(x, xf, n4);
        n4 = G3 * IN_D / 4;
        split_fp16<<<(n4 + 255) / 256, 256>>>(W_ih, wih_h, wih_l, n4);
        n4 = G3 * HID / 4;
        split_fp16<<<(n4 + 255) / 256, 256>>>(W_hh, whh_h, whh_l, n4);
        n4 = N_ENV * HID / 4;
        cvt_fp16<<<(n4 + 255) / 256, 256>>>(hxs, h0, n4);
    }

    // 1) GI = x @ W_ih^T + b_ih.
    {
        dim3 grid(G3 / 64, (T_STEPS * N_ENV) / 128);
        gemm_gi<<<grid, 256>>>(xf, wih_h, wih_l, b_ih, gi, G3, IN_D);
    }

    // 2) Persistent fused scan.
    {
        size_t smem = (size_t)SMEM_ELEMS * sizeof(__half);
        cudaFuncSetAttribute(gru_scan, cudaFuncAttributeMaxDynamicSharedMemorySize,
                             (int)smem);
        dim3 grid(HID / 32, N_ENV / 64);   // 16 x 8 = 128 CTAs
        gru_scan<<<grid, 256, smem>>>(gi, masks, hxs, b_hh, out, h0, h1);
    }

    // 3) h_last to tail before LN rewrites rows.
    copy_hlast<<<(N_ENV * HID / 4) / 256, 256>>>(
        out + (size_t)(T_STEPS - 1) * N_ENV * HID,
        out + (size_t)T_STEPS * N_ENV * HID);

    // 4) In-place LayerNorm.
    layernorm_rows<<<T_STEPS * N_ENV, 128>>>(out, ln_w, ln_b);
}

// round 9
// speedup vs baseline: 3.9948x; 1.0271x over previous
#include <cuda_runtime.h>
#include <cuda_fp16.h>
#include <cstdint>
#include <math.h>

#define T_STEPS 128
#define N_ENV   512
#define IN_D    512
#define HID     512
#define G3      (3 * HID)      // 1536
#define LN_EPS  1e-5f

// ---------------------------------------------------------------------------
// Persistent scratch. gi now fp16 (halves DRAM traffic both sides).
// ---------------------------------------------------------------------------
__device__ __half g_gi[(size_t)T_STEPS * N_ENV * G3];         // 201 MB
__device__ __half g_xf[(size_t)T_STEPS * N_ENV * IN_D];       // 67 MB
__device__ __half g_wih_h[(size_t)G3 * IN_D];
__device__ __half g_wih_l[(size_t)G3 * IN_D];
__device__ __half g_whh_h[(size_t)G3 * HID];
__device__ __half g_whh_l[(size_t)G3 * HID];
__device__ __half g_h0[(size_t)N_ENV * HID];                  // ping-pong h
__device__ __half g_h1[(size_t)N_ENV * HID];
__device__ unsigned g_bar8[8];   // per-envgroup barriers

// ---------------------------------------------------------------------------
__global__ void __launch_bounds__(256)
cvt_fp16(const float* __restrict__ src, __half* __restrict__ dst, int n4)
{
    int idx = blockIdx.x * 256 + threadIdx.x;
    if (idx >= n4) return;
    float4 v = ((const float4*)src)[idx];
    ((__half2*)dst)[2 * idx]     = __floats2half2_rn(v.x, v.y);
    ((__half2*)dst)[2 * idx + 1] = __floats2half2_rn(v.z, v.w);
}

__global__ void __launch_bounds__(256)
split_fp16(const float* __restrict__ src, __half* __restrict__ hi,
           __half* __restrict__ lo, int n4)
{
    int idx = blockIdx.x * 256 + threadIdx.x;
    if (idx >= n4) return;
    float4 v = ((const float4*)src)[idx];
    __half h0 = __float2half_rn(v.x);
    __half h1 = __float2half_rn(v.y);
    __half h2 = __float2half_rn(v.z);
    __half h3 = __float2half_rn(v.w);
    __half l0 = __float2half_rn(v.x - __half2float(h0));
    __half l1 = __float2half_rn(v.y - __half2float(h1));
    __half l2 = __float2half_rn(v.z - __half2float(h2));
    __half l3 = __float2half_rn(v.w - __half2float(h3));
    ((__half2*)hi)[2 * idx]     = __halves2half2(h0, h1);
    ((__half2*)hi)[2 * idx + 1] = __halves2half2(h2, h3);
    ((__half2*)lo)[2 * idx]     = __halves2half2(l0, l1);
    ((__half2*)lo)[2 * idx + 1] = __halves2half2(l2, l3);
}

// ---------------------------------------------------------------------------
__device__ __forceinline__ void ldsm_x4(uint32_t& r0, uint32_t& r1,
                                        uint32_t& r2, uint32_t& r3,
                                        uint32_t addr)
{
    asm volatile("ldmatrix.sync.aligned.m8n8.x4.shared.b16 {%0,%1,%2,%3}, [%4];\n"
                 : "=r"(r0), "=r"(r1), "=r"(r2), "=r"(r3) : "r"(addr));
}

__device__ __forceinline__ void mma_f32(float* c, const uint32_t* a,
                                        uint32_t b0, uint32_t b1)
{
    asm volatile("mma.sync.aligned.m16n8k16.row.col.f32.f16.f16.f32 "
                 "{%0,%1,%2,%3},{%4,%5,%6,%7},{%8,%9},{%0,%1,%2,%3};\n"
                 : "+f"(c[0]), "+f"(c[1]), "+f"(c[2]), "+f"(c[3])
                 : "r"(a[0]), "r"(a[1]), "r"(a[2]), "r"(a[3]), "r"(b0), "r"(b1));
}

__device__ __forceinline__ void mma_f16(uint32_t* c, const uint32_t* a,
                                        uint32_t b0, uint32_t b1)
{
    asm volatile("mma.sync.aligned.m16n8k16.row.col.f16.f16.f16.f16 "
                 "{%0,%1},{%2,%3,%4,%5},{%6,%7},{%0,%1};\n"
                 : "+r"(c[0]), "+r"(c[1])
                 : "r"(a[0]), "r"(a[1]), "r"(a[2]), "r"(a[3]), "r"(b0), "r"(b1));
}

// ===========================================================================
// GI GEMM: gi_fp16[M,1536] = x_fp16 @ (Wh + Wl)^T + bias
// CTA tile 128x64 (256 threads, 8 warps 4x2), BK=64.
// ===========================================================================
#define SSTQ 72

__global__ void __launch_bounds__(256)
gemm_gi(const __half* __restrict__ A, const __half* __restrict__ Bh,
        const __half* __restrict__ Bl, const float* __restrict__ bias,
        __half* __restrict__ C, int Nc, int K)
{
    __shared__ __half sA[128 * SSTQ];
    __shared__ __half sBh[64 * SSTQ], sBl[64 * SSTQ];

    const int tid  = threadIdx.x;
    const int w    = tid >> 5;
    const int lane = tid & 31;
    const int bm   = blockIdx.y * 128;
    const int bn   = blockIdx.x * 64;
    const int wm   = (w & 3) * 32;
    const int wn   = (w >> 2) * 32;

    float acc[2][4][4];
    uint32_t accL[2][4][2];
#pragma unroll
    for (int i = 0; i < 2; ++i)
#pragma unroll
        for (int j = 0; j < 4; ++j) {
#pragma unroll
            for (int k = 0; k < 4; ++k) acc[i][j][k] = 0.0f;
            accL[i][j][0] = 0u; accL[i][j][1] = 0u;
        }

    const uint32_t sAB  = (uint32_t)__cvta_generic_to_shared(sA);
    const uint32_t sBhB = (uint32_t)__cvta_generic_to_shared(sBh);
    const uint32_t sBlB = (uint32_t)__cvta_generic_to_shared(sBl);

    const int a_row = wm + (lane & 7) + ((lane >> 3) & 1) * 8;
    const int a_k   = (lane >> 4) << 3;
    const int b_row = wn + (lane & 7) + ((lane >> 4) << 3);
    const int b_k   = ((lane >> 3) & 1) << 3;

    for (int k0 = 0; k0 < K; k0 += 64) {
#pragma unroll
        for (int i = 0; i < 4; ++i) {
            int idx = tid + i * 256;
            int row = idx >> 3;
            int kc  = (idx & 7) << 3;
            size_t ga = (size_t)(bm + row) * K + k0 + kc;
            int s = row * SSTQ + kc;
            uint4 va = *(const uint4*)(A + ga);
            *(uint2*)&sA[s]     = make_uint2(va.x, va.y);
            *(uint2*)&sA[s + 4] = make_uint2(va.z, va.w);
        }
#pragma unroll
        for (int i = 0; i < 2; ++i) {
            int idx = tid + i * 256;
            int row = idx >> 3;
            int kc  = (idx & 7) << 3;
            size_t gb = (size_t)(bn + row) * K + k0 + kc;
            int s = row * SSTQ + kc;
            uint4 wh = *(const uint4*)(Bh + gb);
            uint4 wl = *(const uint4*)(Bl + gb);
            *(uint2*)&sBh[s]     = make_uint2(wh.x, wh.y);
            *(uint2*)&sBh[s + 4] = make_uint2(wh.z, wh.w);
            *(uint2*)&sBl[s]     = make_uint2(wl.x, wl.y);
            *(uint2*)&sBl[s + 4] = make_uint2(wl.z, wl.w);
        }
        __syncthreads();

#pragma unroll
        for (int kk = 0; kk < 64; kk += 16) {
            const uint32_t mstep = 16 * SSTQ * 2;
            uint32_t aoff = (uint32_t)((a_row * SSTQ + kk + a_k) * 2);
            uint32_t boff = (uint32_t)((b_row * SSTQ + kk + b_k) * 2);

            uint32_t a0[4], a1[4];
            ldsm_x4(a0[0], a0[1], a0[2], a0[3], sAB + aoff);
            ldsm_x4(a1[0], a1[1], a1[2], a1[3], sAB + aoff + mstep);

            uint32_t bh0[4], bh1[4], bl0[4], bl1[4];
            ldsm_x4(bh0[0], bh0[1], bh0[2], bh0[3], sBhB + boff);
            ldsm_x4(bh1[0], bh1[1], bh1[2], bh1[3], sBhB + boff + mstep);
            ldsm_x4(bl0[0], bl0[1], bl0[2], bl0[3], sBlB + boff);
            ldsm_x4(bl1[0], bl1[1], bl1[2], bl1[3], sBlB + boff + mstep);

#pragma unroll
            for (int mt = 0; mt < 2; ++mt) {
                const uint32_t* aP = mt ? a1 : a0;
#pragma unroll
                for (int nt = 0; nt < 4; ++nt) {
                    const uint32_t* bH = (nt < 2) ? bh0 : bh1;
                    const uint32_t* bL = (nt < 2) ? bl0 : bl1;
                    int p = (nt & 1) * 2;
                    mma_f32(acc[mt][nt], aP, bH[p], bH[p + 1]);
                    mma_f16(accL[mt][nt], aP, bL[p], bL[p + 1]);
                }
            }
        }
        __syncthreads();
    }

#pragma unroll
    for (int mt = 0; mt < 2; ++mt) {
#pragma unroll
        for (int nt = 0; nt < 4; ++nt) {
            int r0 = bm + wm + mt * 16 + (lane >> 2);
            int cg = bn + wn + nt * 8 + ((lane & 3) << 1);
            float b0 = bias[cg], b1 = bias[cg + 1];
            float2 l01 = __half22float2(*(__half2*)&accL[mt][nt][0]);
            float2 l23 = __half22float2(*(__half2*)&accL[mt][nt][1]);
            *(__half2*)(C + (size_t)r0 * Nc + cg) =
                __floats2half2_rn(acc[mt][nt][0] + l01.x + b0,
                                  acc[mt][nt][1] + l01.y + b1);
            *(__half2*)(C + (size_t)(r0 + 8) * Nc + cg) =
                __floats2half2_rn(acc[mt][nt][2] + l23.x + b0,
                                  acc[mt][nt][3] + l23.y + b1);
        }
    }
}

// ===========================================================================
// Persistent fused GRU scan. Grid (16, 8) = 128 CTAs x 256 threads.
// Per-envgroup barrier (16 CTAs) — groups are fully data-independent.
// Writes h_last tail at t = T-1.
// ===========================================================================
#define WSTR 520
#define HSTR 136
#define SM_WH 0
#define SM_WL (96 * WSTR)
#define SM_H  (2 * 96 * WSTR)
#define SMEM_ELEMS (2 * 96 * WSTR + 64 * HSTR)   // 217 KB

__global__ void __launch_bounds__(256)
gru_scan(const __half* __restrict__ gi_all, const float* __restrict__ masks,
         const float* __restrict__ hxs, const float* __restrict__ b_hh,
         float* __restrict__ out,
         __half* __restrict__ h0, __half* __restrict__ h1)
{
    extern __shared__ __half sm[];
    __half* sWh = sm + SM_WH;
    __half* sWl = sm + SM_WL;
    __half* sH  = sm + SM_H;

    const int tid  = threadIdx.x;
    const int w    = tid >> 5;
    const int lane = tid & 31;
    const int wq   = w >> 1;
    const int wr   = w & 1;
    const int c0   = blockIdx.x * 32;
    const int gy   = blockIdx.y;
    const int bm   = gy * 64;

    const uint32_t sWhB = (uint32_t)__cvta_generic_to_shared(sWh);
    const uint32_t sWlB = (uint32_t)__cvta_generic_to_shared(sWl);
    const uint32_t sHB  = (uint32_t)__cvta_generic_to_shared(sH);

    // ---- stage W_hh slice once ----
    for (int i = tid; i < 96 * 64; i += 256) {
        int row = i >> 6;
        int seg = (i & 63) << 3;
        int ch  = row >> 5;
        int c   = row & 31;
        size_t g = (size_t)(ch * HID + c0 + c) * HID + seg;
        *(uint4*)&sWh[row * WSTR + seg] = *(const uint4*)&g_whh_h[g];
        *(uint4*)&sWl[row * WSTR + seg] = *(const uint4*)&g_whh_l[g];
    }

    const int env0 = bm + wq * 16 + (lane >> 2);
    const int env1 = env0 + 8;
    const int colbase = c0 + wr * 16;

    float bh[3][2][2], hprev[2][2][2];
#pragma unroll
    for (int ch = 0; ch < 3; ++ch)
#pragma unroll
        for (int nt = 0; nt < 2; ++nt) {
            int col = colbase + nt * 8 + ((lane & 3) << 1);
            bh[ch][nt][0] = b_hh[ch * HID + col];
            bh[ch][nt][1] = b_hh[ch * HID + col + 1];
        }
#pragma unroll
    for (int e = 0; e < 2; ++e)
#pragma unroll
        for (int nt = 0; nt < 2; ++nt) {
            int env = e ? env1 : env0;
            int col = colbase + nt * 8 + ((lane & 3) << 1);
            float2 v = *(const float2*)&hxs[(size_t)env * HID + col];
            hprev[e][nt][0] = v.x; hprev[e][nt][1] = v.y;
        }

    const int a_row = wq * 16 + (lane & 7) + (((lane >> 3) & 1) << 3);
    const int a_k   = (lane >> 4) << 3;
    const int b_rowL = wr * 16 + (lane & 7) + ((lane >> 4) << 3);
    const int b_k   = ((lane >> 3) & 1) << 3;

    const int st_row = tid >> 2;
    const int st_seg = (tid & 3) << 5;

    __syncthreads();

    for (int t = 0; t < T_STEPS; ++t) {
        const __half* Rd = (t & 1) ? h1 : h0;
        __half* Wr = (t & 1) ? h0 : h1;
        const float* mrow = masks + (size_t)t * N_ENV;

        float m_st = mrow[bm + st_row];
        float m_e0 = mrow[env0];
        float m_e1 = mrow[env1];

        // prefetch gate inputs (fp16) early
        float grv[2][2][2], gzv[2][2][2], gnv[2][2][2];
        {
            const __half* gip = gi_all + (size_t)t * N_ENV * G3;
#pragma unroll
            for (int e = 0; e < 2; ++e) {
                int env = e ? env1 : env0;
#pragma unroll
                for (int nt = 0; nt < 2; ++nt) {
                    int col = colbase + nt * 8 + ((lane & 3) << 1);
                    size_t gb = (size_t)env * G3 + col;
                    float2 a = __half22float2(*(const __half2*)&gip[gb]);
                    float2 b = __half22float2(*(const __half2*)&gip[gb + HID]);
                    float2 c = __half22float2(*(const __half2*)&gip[gb + 2 * HID]);
                    grv[e][nt][0] = a.x; grv[e][nt][1] = a.y;
                    gzv[e][nt][0] = b.x; gzv[e][nt][1] = b.y;
                    gnv[e][nt][0] = c.x; gnv[e][nt][1] = c.y;
                }
            }
        }

        float acc[3][2][4];
        uint32_t accL[3][2][2];
#pragma unroll
        for (int ch = 0; ch < 3; ++ch)
#pragma unroll
            for (int nt = 0; nt < 2; ++nt) {
#pragma unroll
                for (int j = 0; j < 4; ++j) acc[ch][nt][j] = 0.0f;
                accL[ch][nt][0] = 0u; accL[ch][nt][1] = 0u;
            }

        uint4 pv[4], nv[4];
        {
            size_t g = (size_t)(bm + st_row) * HID + st_seg;
#pragma unroll
            for (int j = 0; j < 4; ++j) pv[j] = *(const uint4*)&Rd[g + j * 8];
        }

        for (int cnk = 0; cnk < 4; ++cnk) {
            __syncthreads();
            {
                uint4 z = make_uint4(0, 0, 0, 0);
                int s = st_row * HSTR + st_seg;
#pragma unroll
                for (int j = 0; j < 4; ++j)
                    *(uint4*)&sH[s + j * 8] = (m_st == 0.0f) ? z : pv[j];
            }
            if (cnk < 3) {
                size_t g = (size_t)(bm + st_row) * HID + (cnk + 1) * 128 + st_seg;
#pragma unroll
                for (int j = 0; j < 4; ++j) nv[j] = *(const uint4*)&Rd[g + j * 8];
            }
            __syncthreads();

            const int k0 = cnk * 128;
#pragma unroll
            for (int kk = 0; kk < 128; kk += 16) {
                uint32_t aoff = (uint32_t)((a_row * HSTR + kk + a_k) * 2);
                uint32_t ah[4];
                ldsm_x4(ah[0], ah[1], ah[2], ah[3], sHB + aoff);

#pragma unroll
                for (int ch = 0; ch < 3; ++ch) {
                    uint32_t boff = (uint32_t)(((ch * 32 + b_rowL) * WSTR
                                               + k0 + kk + b_k) * 2);
                    uint32_t bhk[4], blk[4];
                    ldsm_x4(bhk[0], bhk[1], bhk[2], bhk[3], sWhB + boff);
                    ldsm_x4(blk[0], blk[1], blk[2], blk[3], sWlB + boff);
#pragma unroll
                    for (int nt = 0; nt < 2; ++nt) {
                        int p = nt * 2;
                        mma_f32(acc[ch][nt], ah, bhk[p], bhk[p + 1]);
                        mma_f16(accL[ch][nt], ah, blk[p], blk[p + 1]);
                    }
                }
            }
#pragma unroll
            for (int j = 0; j < 4; ++j) pv[j] = nv[j];
        }

        // ---- fused gate ----
#pragma unroll
        for (int e = 0; e < 2; ++e) {
            int env = e ? env1 : env0;
            float m = e ? m_e1 : m_e0;
#pragma unroll
            for (int nt = 0; nt < 2; ++nt) {
                int col = colbase + nt * 8 + ((lane & 3) << 1);
                int j0 = 2 * e;
                float2 lr = __half22float2(*(__half2*)&accL[0][nt][e]);
                float2 lz = __half22float2(*(__half2*)&accL[1][nt][e]);
                float2 ln = __half22float2(*(__half2*)&accL[2][nt][e]);

                float hr0 = acc[0][nt][j0]     + lr.x + bh[0][nt][0];
                float hr1 = acc[0][nt][j0 + 1] + lr.y + bh[0][nt][1];
                float hz0 = acc[1][nt][j0]     + lz.x + bh[1][nt][0];
                float hz1 = acc[1][nt][j0 + 1] + lz.y + bh[1][nt][1];
                float hn0 = acc[2][nt][j0]     + ln.x + bh[2][nt][0];
                float hn1 = acc[2][nt][j0 + 1] + ln.y + bh[2][nt][1];

                float r0 = 1.0f / (1.0f + __expf(-(grv[e][nt][0] + hr0)));
                float r1 = 1.0f / (1.0f + __expf(-(grv[e][nt][1] + hr1)));
                float z0 = 1.0f / (1.0f + __expf(-(gzv[e][nt][0] + hz0)));
                float z1 = 1.0f / (1.0f + __expf(-(gzv[e][nt][1] + hz1)));
                float n0 = tanhf(gnv[e][nt][0] + r0 * hn0);
                float n1 = tanhf(gnv[e][nt][1] + r1 * hn1);

                float h0v = hprev[e][nt][0] * m;
                float h1v = hprev[e][nt][1] * m;
                float hw0 = (1.0f - z0) * n0 + z0 * h0v;
                float hw1 = (1.0f - z1) * n1 + z1 * h1v;
                hprev[e][nt][0] = hw0;
                hprev[e][nt][1] = hw1;

                *(float2*)&out[(size_t)t * N_ENV * HID + (size_t)env * HID + col]
                    = make_float2(hw0, hw1);
                *(__half2*)&Wr[(size_t)env * HID + col]
                    = __floats2half2_rn(hw0, hw1);
                if (t == T_STEPS - 1) {
                    *(float2*)&out[(size_t)T_STEPS * N_ENV * HID
                                   + (size_t)env * HID + col]
                        = make_float2(hw0, hw1);
                }
            }
        }

        // ---- per-envgroup barrier (16 CTAs sharing gy) ----
        if (t < T_STEPS - 1) {
            __threadfence();
            __syncthreads();
            if (tid == 0) {
                atomicAdd(&g_bar8[gy], 1u);
                unsigned target = 16u * (unsigned)(t + 1);
                while (*(volatile unsigned*)&g_bar8[gy] < target) { }
            }
            __syncthreads();
            __threadfence();
        }
    }
}

// ---------------------------------------------------------------------------
__global__ void __launch_bounds__(128)
layernorm_rows(float* __restrict__ data, const float* __restrict__ w,
               const float* __restrict__ b)
{
    __shared__ float ss[4], sqs[4];
    float* p = data + (size_t)blockIdx.x * HID;
    int t = threadIdx.x;

    float4 v = ((const float4*)p)[t];
    float s  = v.x + v.y + v.z + v.w;
    float sq = v.x * v.x + v.y * v.y + v.z * v.z + v.w * v.w;

#pragma unroll
    for (int o = 16; o > 0; o >>= 1) {
        s  += __shfl_xor_sync(0xffffffffu, s,  o);
        sq += __shfl_xor_sync(0xffffffffu, sq, o);
    }
    int warp = t >> 5;
    if ((t & 31) == 0) { ss[warp] = s; sqs[warp] = sq; }
    __syncthreads();
    s  = ss[0]  + ss[1]  + ss[2]  + ss[3];
    sq = sqs[0] + sqs[1] + sqs[2] + sqs[3];

    float mu  = s * (1.0f / HID);
    float var = sq * (1.0f / HID) - mu * mu;
    float inv = rsqrtf(var + LN_EPS);

    float4 wv = ((const float4*)w)[t];
    float4 bv = ((const float4*)b)[t];
    float4 o;
    o.x = (v.x - mu) * inv * wv.x + bv.x;
    o.y = (v.y - mu) * inv * wv.y + bv.y;
    o.z = (v.z - mu) * inv * wv.z + bv.z;
    o.w = (v.w - mu) * inv * wv.w + bv.w;
    ((float4*)p)[t] = o;
}

// ---------------------------------------------------------------------------
extern "C" void kernel_launch(void* const* d_in, const int* in_sizes, int n_in,
                              void* d_out, int out_size)
{
    const float* x     = (const float*)d_in[0];
    const float* hxs   = (const float*)d_in[1];
    const float* masks = (const float*)d_in[2];
    const float* W_ih  = (const float*)d_in[3];
    const float* W_hh  = (const float*)d_in[4];
    const float* b_ih  = (const float*)d_in[5];
    const float* b_hh  = (const float*)d_in[6];
    const float* ln_w  = (const float*)d_in[7];
    const float* ln_b  = (const float*)d_in[8];
    float* out = (float*)d_out;

    __half *gi, *xf, *wih_h, *wih_l, *whh_h, *whh_l, *h0, *h1;
    unsigned* barp;
    cudaGetSymbolAddress((void**)&gi, g_gi);
    cudaGetSymbolAddress((void**)&xf, g_xf);
    cudaGetSymbolAddress((void**)&wih_h, g_wih_h);
    cudaGetSymbolAddress((void**)&wih_l, g_wih_l);
    cudaGetSymbolAddress((void**)&whh_h, g_whh_h);
    cudaGetSymbolAddress((void**)&whh_l, g_whh_l);
    cudaGetSymbolAddress((void**)&h0, g_h0);
    cudaGetSymbolAddress((void**)&h1, g_h1);
    cudaGetSymbolAddress((void**)&barp, g_bar8);

    cudaMemsetAsync(barp, 0, 8 * sizeof(unsigned));

    // 0) One-time conversions.
    {
        int n4;
        n4 = T_STEPS * N_ENV * IN_D / 4;
        cvt_fp16<<<(n4 + 255) / 256, 256>>>(x, xf, n4);
        n4 = G3 * IN_D / 4;
        split_fp16<<<(n4 + 255) / 256, 256>>>(W_ih, wih_h, wih_l, n4);
        n4 = G3 * HID / 4;
        split_fp16<<<(n4 + 255) / 256, 256>>>(W_hh, whh_h, whh_l, n4);
        n4 = N_ENV * HID / 4;
        cvt_fp16<<<(n4 + 255) / 256, 256>>>(hxs, h0, n4);
    }

    // 1) GI = x @ W_ih^T + b_ih (fp16 out).
    {
        dim3 grid(G3 / 64, (T_STEPS * N_ENV) / 128);
        gemm_gi<<<grid, 256>>>(xf, wih_h, wih_l, b_ih, gi, G3, IN_D);
    }

    // 2) Persistent fused scan (writes h_last tail too).
    {
        size_t smem = (size_t)SMEM_ELEMS * sizeof(__half);
        cudaFuncSetAttribute(gru_scan, cudaFuncAttributeMaxDynamicSharedMemorySize,
                             (int)smem);
        dim3 grid(HID / 32, N_ENV / 64);   // 16 x 8 = 128 CTAs
        gru_scan<<<grid, 256, smem>>>(gi, masks, hxs, b_hh, out, h0, h1);
    }

    // 3) In-place LayerNorm.
    layernorm_rows<<<T_STEPS * N_ENV, 128>>>(out, ln_w, ln_b);
}

// round 12
// speedup vs baseline: 5.3966x; 1.3509x over previous
#include <cuda_runtime.h>
#include <cuda_fp16.h>
#include <cstdint>
#include <math.h>

#define T_STEPS 128
#define N_ENV   512
#define IN_D    512
#define HID     512
#define G3      (3 * HID)      // 1536
#define LN_EPS  1e-5f

// ---------------------------------------------------------------------------
// Persistent scratch (fp16 weights, single term).
// ---------------------------------------------------------------------------
__device__ __half g_gi[(size_t)T_STEPS * N_ENV * G3];         // 201 MB
__device__ __half g_xf[(size_t)T_STEPS * N_ENV * IN_D];       // 67 MB
__device__ __half g_wih[(size_t)G3 * IN_D];
__device__ __half g_whh[(size_t)G3 * HID];
__device__ __half g_h0[(size_t)N_ENV * HID];                  // ping-pong h
__device__ __half g_h1[(size_t)N_ENV * HID];
__device__ unsigned g_bar8[8];   // per-envgroup barriers

// ---------------------------------------------------------------------------
__global__ void __launch_bounds__(256)
cvt_fp16(const float* __restrict__ src, __half* __restrict__ dst, int n4)
{
    int idx = blockIdx.x * 256 + threadIdx.x;
    if (idx >= n4) return;
    float4 v = ((const float4*)src)[idx];
    ((__half2*)dst)[2 * idx]     = __floats2half2_rn(v.x, v.y);
    ((__half2*)dst)[2 * idx + 1] = __floats2half2_rn(v.z, v.w);
}

// ---------------------------------------------------------------------------
__device__ __forceinline__ void ldsm_x4(uint32_t& r0, uint32_t& r1,
                                        uint32_t& r2, uint32_t& r3,
                                        uint32_t addr)
{
    asm volatile("ldmatrix.sync.aligned.m8n8.x4.shared.b16 {%0,%1,%2,%3}, [%4];\n"
                 : "=r"(r0), "=r"(r1), "=r"(r2), "=r"(r3) : "r"(addr));
}

__device__ __forceinline__ void mma_f32(float* c, const uint32_t* a,
                                        uint32_t b0, uint32_t b1)
{
    asm volatile("mma.sync.aligned.m16n8k16.row.col.f32.f16.f16.f32 "
                 "{%0,%1,%2,%3},{%4,%5,%6,%7},{%8,%9},{%0,%1,%2,%3};\n"
                 : "+f"(c[0]), "+f"(c[1]), "+f"(c[2]), "+f"(c[3])
                 : "r"(a[0]), "r"(a[1]), "r"(a[2]), "r"(a[3]), "r"(b0), "r"(b1));
}

// ===========================================================================
// GI GEMM: gi_fp16[M,1536] = x_fp16 @ W^T + bias  (single fp16 term)
// CTA tile 128x64 (256 threads, 8 warps 4x2), BK=64.
// ===========================================================================
#define SSTQ 72

__global__ void __launch_bounds__(256)
gemm_gi(const __half* __restrict__ A, const __half* __restrict__ B,
        const float* __restrict__ bias, __half* __restrict__ C, int Nc, int K)
{
    __shared__ __half sA[128 * SSTQ];
    __shared__ __half sB[64 * SSTQ];

    const int tid  = threadIdx.x;
    const int w    = tid >> 5;
    const int lane = tid & 31;
    const int bm   = blockIdx.y * 128;
    const int bn   = blockIdx.x * 64;
    const int wm   = (w & 3) * 32;
    const int wn   = (w >> 2) * 32;

    float acc[2][4][4];
#pragma unroll
    for (int i = 0; i < 2; ++i)
#pragma unroll
        for (int j = 0; j < 4; ++j)
#pragma unroll
            for (int k = 0; k < 4; ++k) acc[i][j][k] = 0.0f;

    const uint32_t sAB = (uint32_t)__cvta_generic_to_shared(sA);
    const uint32_t sBB = (uint32_t)__cvta_generic_to_shared(sB);

    const int a_row = wm + (lane & 7) + ((lane >> 3) & 1) * 8;
    const int a_k   = (lane >> 4) << 3;
    const int b_row = wn + (lane & 7) + ((lane >> 4) << 3);
    const int b_k   = ((lane >> 3) & 1) << 3;

    for (int k0 = 0; k0 < K; k0 += 64) {
#pragma unroll
        for (int i = 0; i < 4; ++i) {
            int idx = tid + i * 256;
            int row = idx >> 3;
            int kc  = (idx & 7) << 3;
            size_t ga = (size_t)(bm + row) * K + k0 + kc;
            int s = row * SSTQ + kc;
            uint4 va = *(const uint4*)(A + ga);
            *(uint2*)&sA[s]     = make_uint2(va.x, va.y);
            *(uint2*)&sA[s + 4] = make_uint2(va.z, va.w);
        }
#pragma unroll
        for (int i = 0; i < 2; ++i) {
            int idx = tid + i * 256;
            int row = idx >> 3;
            int kc  = (idx & 7) << 3;
            size_t gb = (size_t)(bn + row) * K + k0 + kc;
            int s = row * SSTQ + kc;
            uint4 wb = *(const uint4*)(B + gb);
            *(uint2*)&sB[s]     = make_uint2(wb.x, wb.y);
            *(uint2*)&sB[s + 4] = make_uint2(wb.z, wb.w);
        }
        __syncthreads();

#pragma unroll
        for (int kk = 0; kk < 64; kk += 16) {
            const uint32_t mstep = 16 * SSTQ * 2;
            uint32_t aoff = (uint32_t)((a_row * SSTQ + kk + a_k) * 2);
            uint32_t boff = (uint32_t)((b_row * SSTQ + kk + b_k) * 2);

            uint32_t a0[4], a1[4];
            ldsm_x4(a0[0], a0[1], a0[2], a0[3], sAB + aoff);
            ldsm_x4(a1[0], a1[1], a1[2], a1[3], sAB + aoff + mstep);

            uint32_t b0[4], b1[4];
            ldsm_x4(b0[0], b0[1], b0[2], b0[3], sBB + boff);
            ldsm_x4(b1[0], b1[1], b1[2], b1[3], sBB + boff + mstep);

#pragma unroll
            for (int mt = 0; mt < 2; ++mt) {
                const uint32_t* aP = mt ? a1 : a0;
#pragma unroll
                for (int nt = 0; nt < 4; ++nt) {
                    const uint32_t* bP = (nt < 2) ? b0 : b1;
                    int p = (nt & 1) * 2;
                    mma_f32(acc[mt][nt], aP, bP[p], bP[p + 1]);
                }
            }
        }
        __syncthreads();
    }

#pragma unroll
    for (int mt = 0; mt < 2; ++mt) {
#pragma unroll
        for (int nt = 0; nt < 4; ++nt) {
            int r0 = bm + wm + mt * 16 + (lane >> 2);
            int cg = bn + wn + nt * 8 + ((lane & 3) << 1);
            float b0 = bias[cg], b1 = bias[cg + 1];
            *(__half2*)(C + (size_t)r0 * Nc + cg) =
                __floats2half2_rn(acc[mt][nt][0] + b0, acc[mt][nt][1] + b1);
            *(__half2*)(C + (size_t)(r0 + 8) * Nc + cg) =
                __floats2half2_rn(acc[mt][nt][2] + b0, acc[mt][nt][3] + b1);
        }
    }
}

// ===========================================================================
// Persistent fused GRU scan. Grid (16, 8) = 128 CTAs x 256 threads.
// Single fp16 term; FULL 512-K h tile staged once per step (2 syncs/step).
// W_hh slice (96 rows x 512) resident in smem. Per-envgroup barriers.
// ===========================================================================
#define WSTR 520
#define HSTR 520
#define SM_W  0
#define SM_H  (96 * WSTR)
#define SMEM_ELEMS (96 * WSTR + 64 * HSTR)   // 83200 halves = 162.5 KB

__global__ void __launch_bounds__(256)
gru_scan(const __half* __restrict__ gi_all, const float* __restrict__ masks,
         const float* __restrict__ hxs, const float* __restrict__ b_hh,
         float* __restrict__ out,
         __half* __restrict__ h0, __half* __restrict__ h1)
{
    extern __shared__ __half sm[];
    __half* sW = sm + SM_W;
    __half* sH = sm + SM_H;

    const int tid  = threadIdx.x;
    const int w    = tid >> 5;
    const int lane = tid & 31;
    const int wq   = w >> 1;
    const int wr   = w & 1;
    const int c0   = blockIdx.x * 32;
    const int gy   = blockIdx.y;
    const int bm   = gy * 64;

    const uint32_t sWB = (uint32_t)__cvta_generic_to_shared(sW);
    const uint32_t sHB = (uint32_t)__cvta_generic_to_shared(sH);

    // ---- stage W_hh slice once: 96 rows x 512 K ----
    for (int i = tid; i < 96 * 64; i += 256) {
        int row = i >> 6;
        int seg = (i & 63) << 3;
        int ch  = row >> 5;
        int c   = row & 31;
        size_t g = (size_t)(ch * HID + c0 + c) * HID + seg;
        *(uint4*)&sW[row * WSTR + seg] = *(const uint4*)&g_whh[g];
    }

    const int env0 = bm + wq * 16 + (lane >> 2);
    const int env1 = env0 + 8;
    const int colbase = c0 + wr * 16;

    float bh[3][2][2], hprev[2][2][2];
#pragma unroll
    for (int ch = 0; ch < 3; ++ch)
#pragma unroll
        for (int nt = 0; nt < 2; ++nt) {
            int col = colbase + nt * 8 + ((lane & 3) << 1);
            bh[ch][nt][0] = b_hh[ch * HID + col];
            bh[ch][nt][1] = b_hh[ch * HID + col + 1];
        }
#pragma unroll
    for (int e = 0; e < 2; ++e)
#pragma unroll
        for (int nt = 0; nt < 2; ++nt) {
            int env = e ? env1 : env0;
            int col = colbase + nt * 8 + ((lane & 3) << 1);
            float2 v = *(const float2*)&hxs[(size_t)env * HID + col];
            hprev[e][nt][0] = v.x; hprev[e][nt][1] = v.y;
        }

    const int a_row = wq * 16 + (lane & 7) + (((lane >> 3) & 1) << 3);
    const int a_k   = (lane >> 4) << 3;
    const int b_rowL = wr * 16 + (lane & 7) + ((lane >> 4) << 3);
    const int b_k   = ((lane >> 3) & 1) << 3;

    __syncthreads();

    for (int t = 0; t < T_STEPS; ++t) {
        const __half* Rd = (t & 1) ? h1 : h0;
        __half* Wr = (t & 1) ? h0 : h1;
        const float* mrow = masks + (size_t)t * N_ENV;

        float m_e0 = mrow[env0];
        float m_e1 = mrow[env1];

        // ---- prefetch gate inputs (fp16, DRAM) early ----
        float grv[2][2][2], gzv[2][2][2], gnv[2][2][2];
        {
            const __half* gip = gi_all + (size_t)t * N_ENV * G3;
#pragma unroll
            for (int e = 0; e < 2; ++e) {
                int env = e ? env1 : env0;
#pragma unroll
                for (int nt = 0; nt < 2; ++nt) {
                    int col = colbase + nt * 8 + ((lane & 3) << 1);
                    size_t gb = (size_t)env * G3 + col;
                    float2 a = __half22float2(*(const __half2*)&gip[gb]);
                    float2 b = __half22float2(*(const __half2*)&gip[gb + HID]);
                    float2 c = __half22float2(*(const __half2*)&gip[gb + 2 * HID]);
                    grv[e][nt][0] = a.x; grv[e][nt][1] = a.y;
                    gzv[e][nt][0] = b.x; gzv[e][nt][1] = b.y;
                    gnv[e][nt][0] = c.x; gnv[e][nt][1] = c.y;
                }
            }
        }

        // ---- stage full h tile (64 envs x 512 K), mask-zero dead rows ----
        // (previous step's mma reads of sH retired before the barrier syncs)
#pragma unroll 4
        for (int i = tid; i < 64 * 64; i += 256) {
            int row = i >> 6;
            int seg = (i & 63) << 3;
            float m = mrow[bm + row];
            uint4 v = *(const uint4*)&Rd[(size_t)(bm + row) * HID + seg];
            if (m == 0.0f) v = make_uint4(0, 0, 0, 0);
            *(uint4*)&sH[row * HSTR + seg] = v;
        }
        __syncthreads();

        float acc[3][2][4];
#pragma unroll
        for (int ch = 0; ch < 3; ++ch)
#pragma unroll
            for (int nt = 0; nt < 2; ++nt)
#pragma unroll
                for (int j = 0; j < 4; ++j) acc[ch][nt][j] = 0.0f;

#pragma unroll 8
        for (int kk = 0; kk < 512; kk += 16) {
            uint32_t aoff = (uint32_t)((a_row * HSTR + kk + a_k) * 2);
            uint32_t ah[4];
            ldsm_x4(ah[0], ah[1], ah[2], ah[3], sHB + aoff);

#pragma unroll
            for (int ch = 0; ch < 3; ++ch) {
                uint32_t boff = (uint32_t)(((ch * 32 + b_rowL) * WSTR
                                           + kk + b_k) * 2);
                uint32_t bk[4];
                ldsm_x4(bk[0], bk[1], bk[2], bk[3], sWB + boff);
#pragma unroll
                for (int nt = 0; nt < 2; ++nt) {
                    int p = nt * 2;
                    mma_f32(acc[ch][nt], ah, bk[p], bk[p + 1]);
                }
            }
        }

        // ---- fused gate ----
#pragma unroll
        for (int e = 0; e < 2; ++e) {
            int env = e ? env1 : env0;
            float m = e ? m_e1 : m_e0;
#pragma unroll
            for (int nt = 0; nt < 2; ++nt) {
                int col = colbase + nt * 8 + ((lane & 3) << 1);
                int j0 = 2 * e;

                float hr0 = acc[0][nt][j0]     + bh[0][nt][0];
                float hr1 = acc[0][nt][j0 + 1] + bh[0][nt][1];
                float hz0 = acc[1][nt][j0]     + bh[1][nt][0];
                float hz1 = acc[1][nt][j0 + 1] + bh[1][nt][1];
                float hn0 = acc[2][nt][j0]     + bh[2][nt][0];
                float hn1 = acc[2][nt][j0 + 1] + bh[2][nt][1];

                float r0 = 1.0f / (1.0f + __expf(-(grv[e][nt][0] + hr0)));
                float r1 = 1.0f / (1.0f + __expf(-(grv[e][nt][1] + hr1)));
                float z0 = 1.0f / (1.0f + __expf(-(gzv[e][nt][0] + hz0)));
                float z1 = 1.0f / (1.0f + __expf(-(gzv[e][nt][1] + hz1)));
                float n0 = tanhf(gnv[e][nt][0] + r0 * hn0);
                float n1 = tanhf(gnv[e][nt][1] + r1 * hn1);

                float h0v = hprev[e][nt][0] * m;
                float h1v = hprev[e][nt][1] * m;
                float hw0 = (1.0f - z0) * n0 + z0 * h0v;
                float hw1 = (1.0f - z1) * n1 + z1 * h1v;
                hprev[e][nt][0] = hw0;
                hprev[e][nt][1] = hw1;

                *(float2*)&out[(size_t)t * N_ENV * HID + (size_t)env * HID + col]
                    = make_float2(hw0, hw1);
                *(__half2*)&Wr[(size_t)env * HID + col]
                    = __floats2half2_rn(hw0, hw1);
                if (t == T_STEPS - 1) {
                    *(float2*)&out[(size_t)T_STEPS * N_ENV * HID
                                   + (size_t)env * HID + col]
                        = make_float2(hw0, hw1);
                }
            }
        }

        // ---- per-envgroup barrier (16 CTAs sharing gy) ----
        if (t < T_STEPS - 1) {
            __threadfence();
            __syncthreads();
            if (tid == 0) {
                atomicAdd(&g_bar8[gy], 1u);
                unsigned target = 16u * (unsigned)(t + 1);
                while (*(volatile unsigned*)&g_bar8[gy] < target) { }
            }
            __syncthreads();
            __threadfence();
        }
    }
}

// ---------------------------------------------------------------------------
__global__ void __launch_bounds__(128)
layernorm_rows(float* __restrict__ data, const float* __restrict__ w,
               const float* __restrict__ b)
{
    __shared__ float ss[4], sqs[4];
    float* p = data + (size_t)blockIdx.x * HID;
    int t = threadIdx.x;

    float4 v = ((const float4*)p)[t];
    float s  = v.x + v.y + v.z + v.w;
    float sq = v.x * v.x + v.y * v.y + v.z * v.z + v.w * v.w;

#pragma unroll
    for (int o = 16; o > 0; o >>= 1) {
        s  += __shfl_xor_sync(0xffffffffu, s,  o);
        sq += __shfl_xor_sync(0xffffffffu, sq, o);
    }
    int warp = t >> 5;
    if ((t & 31) == 0) { ss[warp] = s; sqs[warp] = sq; }
    __syncthreads();
    s  = ss[0]  + ss[1]  + ss[2]  + ss[3];
    sq = sqs[0] + sqs[1] + sqs[2] + sqs[3];

    float mu  = s * (1.0f / HID);
    float var = sq * (1.0f / HID) - mu * mu;
    float inv = rsqrtf(var + LN_EPS);

    float4 wv = ((const float4*)w)[t];
    float4 bv = ((const float4*)b)[t];
    float4 o;
    o.x = (v.x - mu) * inv * wv.x + bv.x;
    o.y = (v.y - mu) * inv * wv.y + bv.y;
    o.z = (v.z - mu) * inv * wv.z + bv.z;
    o.w = (v.w - mu) * inv * wv.w + bv.w;
    ((float4*)p)[t] = o;
}

// ---------------------------------------------------------------------------
extern "C" void kernel_launch(void* const* d_in, const int* in_sizes, int n_in,
                              void* d_out, int out_size)
{
    const float* x     = (const float*)d_in[0];
    const float* hxs   = (const float*)d_in[1];
    const float* masks = (const float*)d_in[2];
    const float* W_ih  = (const float*)d_in[3];
    const float* W_hh  = (const float*)d_in[4];
    const float* b_ih  = (const float*)d_in[5];
    const float* b_hh  = (const float*)d_in[6];
    const float* ln_w  = (const float*)d_in[7];
    const float* ln_b  = (const float*)d_in[8];
    float* out = (float*)d_out;

    __half *gi, *xf, *wih, *whh, *h0, *h1;
    unsigned* barp;
    cudaGetSymbolAddress((void**)&gi, g_gi);
    cudaGetSymbolAddress((void**)&xf, g_xf);
    cudaGetSymbolAddress((void**)&wih, g_wih);
    cudaGetSymbolAddress((void**)&whh, g_whh);
    cudaGetSymbolAddress((void**)&h0, g_h0);
    cudaGetSymbolAddress((void**)&h1, g_h1);
    cudaGetSymbolAddress((void**)&barp, g_bar8);

    cudaMemsetAsync(barp, 0, 8 * sizeof(unsigned));

    // 0) One-time fp32 -> fp16 conversions.
    {
        int n4;
        n4 = T_STEPS * N_ENV * IN_D / 4;
        cvt_fp16<<<(n4 + 255) / 256, 256>>>(x, xf, n4);
        n4 = G3 * IN_D / 4;
        cvt_fp16<<<(n4 + 255) / 256, 256>>>(W_ih, wih, n4);
        n4 = G3 * HID / 4;
        cvt_fp16<<<(n4 + 255) / 256, 256>>>(W_hh, whh, n4);
        n4 = N_ENV * HID / 4;
        cvt_fp16<<<(n4 + 255) / 256, 256>>>(hxs, h0, n4);
    }

    // 1) GI = x @ W_ih^T + b_ih (fp16 out).
    {
        dim3 grid(G3 / 64, (T_STEPS * N_ENV) / 128);
        gemm_gi<<<grid, 256>>>(xf, wih, b_ih, gi, G3, IN_D);
    }

    // 2) Persistent fused scan (writes h_last tail too).
    {
        size_t smem = (size_t)SMEM_ELEMS * sizeof(__half);
        cudaFuncSetAttribute(gru_scan, cudaFuncAttributeMaxDynamicSharedMemorySize,
                             (int)smem);
        dim3 grid(HID / 32, N_ENV / 64);   // 16 x 8 = 128 CTAs
        gru_scan<<<grid, 256, smem>>>(gi, masks, hxs, b_hh, out, h0, h1);
    }

    // 3) In-place LayerNorm.
    layernorm_rows<<<T_STEPS * N_ENV, 128>>>(out, ln_w, ln_b);
}

// round 13
// speedup vs baseline: 5.8199x; 1.0784x over previous
#include <cuda_runtime.h>
#include <cuda_fp16.h>
#include <cstdint>
#include <math.h>

#define T_STEPS 128
#define N_ENV   512
#define IN_D    512
#define HID     512
#define G3      (3 * HID)      // 1536
#define LN_EPS  1e-5f

// ---------------------------------------------------------------------------
// Persistent scratch. g_xf doubles as the h history buffer: the GI GEMM
// consumes x_fp16 fully before the scan launches, then the scan overwrites
// it with hist[t][env][col] (fp16 h per step) which LayerNorm reads.
// ---------------------------------------------------------------------------
__device__ __half g_gi[(size_t)T_STEPS * N_ENV * G3];         // 201 MB
__device__ __half g_xf[(size_t)T_STEPS * N_ENV * IN_D];       // 67 MB (x, then hist)
__device__ __half g_wih[(size_t)G3 * IN_D];
__device__ __half g_whh[(size_t)G3 * HID];
__device__ __half g_h0[(size_t)N_ENV * HID];                  // initial h (fp16)
__device__ unsigned g_bar8[8];   // per-envgroup barriers

// ---------------------------------------------------------------------------
__global__ void __launch_bounds__(256)
cvt_fp16(const float* __restrict__ src, __half* __restrict__ dst, int n4)
{
    int idx = blockIdx.x * 256 + threadIdx.x;
    if (idx >= n4) return;
    float4 v = ((const float4*)src)[idx];
    ((__half2*)dst)[2 * idx]     = __floats2half2_rn(v.x, v.y);
    ((__half2*)dst)[2 * idx + 1] = __floats2half2_rn(v.z, v.w);
}

// ---------------------------------------------------------------------------
__device__ __forceinline__ void ldsm_x4(uint32_t& r0, uint32_t& r1,
                                        uint32_t& r2, uint32_t& r3,
                                        uint32_t addr)
{
    asm volatile("ldmatrix.sync.aligned.m8n8.x4.shared.b16 {%0,%1,%2,%3}, [%4];\n"
                 : "=r"(r0), "=r"(r1), "=r"(r2), "=r"(r3) : "r"(addr));
}

__device__ __forceinline__ void mma_f32(float* c, const uint32_t* a,
                                        uint32_t b0, uint32_t b1)
{
    asm volatile("mma.sync.aligned.m16n8k16.row.col.f32.f16.f16.f32 "
                 "{%0,%1,%2,%3},{%4,%5,%6,%7},{%8,%9},{%0,%1,%2,%3};\n"
                 : "+f"(c[0]), "+f"(c[1]), "+f"(c[2]), "+f"(c[3])
                 : "r"(a[0]), "r"(a[1]), "r"(a[2]), "r"(a[3]), "r"(b0), "r"(b1));
}

__device__ __forceinline__ float fast_sigmoid(float x)
{
    return __fdividef(1.0f, 1.0f + __expf(-x));
}

__device__ __forceinline__ float fast_tanh(float x)
{
    float t = __expf(2.0f * x);
    return __fdividef(t - 1.0f, t + 1.0f);
}

// ===========================================================================
// GI GEMM: gi_fp16[M,1536] = x_fp16 @ W^T + bias  (single fp16 term)
// CTA tile 128x64 (256 threads, 8 warps 4x2), BK=64.
// ===========================================================================
#define SSTQ 72

__global__ void __launch_bounds__(256)
gemm_gi(const __half* __restrict__ A, const __half* __restrict__ B,
        const float* __restrict__ bias, __half* __restrict__ C, int Nc, int K)
{
    __shared__ __half sA[128 * SSTQ];
    __shared__ __half sB[64 * SSTQ];

    const int tid  = threadIdx.x;
    const int w    = tid >> 5;
    const int lane = tid & 31;
    const int bm   = blockIdx.y * 128;
    const int bn   = blockIdx.x * 64;
    const int wm   = (w & 3) * 32;
    const int wn   = (w >> 2) * 32;

    float acc[2][4][4];
#pragma unroll
    for (int i = 0; i < 2; ++i)
#pragma unroll
        for (int j = 0; j < 4; ++j)
#pragma unroll
            for (int k = 0; k < 4; ++k) acc[i][j][k] = 0.0f;

    const uint32_t sAB = (uint32_t)__cvta_generic_to_shared(sA);
    const uint32_t sBB = (uint32_t)__cvta_generic_to_shared(sB);

    const int a_row = wm + (lane & 7) + ((lane >> 3) & 1) * 8;
    const int a_k   = (lane >> 4) << 3;
    const int b_row = wn + (lane & 7) + ((lane >> 4) << 3);
    const int b_k   = ((lane >> 3) & 1) << 3;

    for (int k0 = 0; k0 < K; k0 += 64) {
#pragma unroll
        for (int i = 0; i < 4; ++i) {
            int idx = tid + i * 256;
            int row = idx >> 3;
            int kc  = (idx & 7) << 3;
            size_t ga = (size_t)(bm + row) * K + k0 + kc;
            int s = row * SSTQ + kc;
            uint4 va = *(const uint4*)(A + ga);
            *(uint2*)&sA[s]     = make_uint2(va.x, va.y);
            *(uint2*)&sA[s + 4] = make_uint2(va.z, va.w);
        }
#pragma unroll
        for (int i = 0; i < 2; ++i) {
            int idx = tid + i * 256;
            int row = idx >> 3;
            int kc  = (idx & 7) << 3;
            size_t gb = (size_t)(bn + row) * K + k0 + kc;
            int s = row * SSTQ + kc;
            uint4 wb = *(const uint4*)(B + gb);
            *(uint2*)&sB[s]     = make_uint2(wb.x, wb.y);
            *(uint2*)&sB[s + 4] = make_uint2(wb.z, wb.w);
        }
        __syncthreads();

#pragma unroll
        for (int kk = 0; kk < 64; kk += 16) {
            const uint32_t mstep = 16 * SSTQ * 2;
            uint32_t aoff = (uint32_t)((a_row * SSTQ + kk + a_k) * 2);
            uint32_t boff = (uint32_t)((b_row * SSTQ + kk + b_k) * 2);

            uint32_t a0[4], a1[4];
            ldsm_x4(a0[0], a0[1], a0[2], a0[3], sAB + aoff);
            ldsm_x4(a1[0], a1[1], a1[2], a1[3], sAB + aoff + mstep);

            uint32_t b0[4], b1[4];
            ldsm_x4(b0[0], b0[1], b0[2], b0[3], sBB + boff);
            ldsm_x4(b1[0], b1[1], b1[2], b1[3], sBB + boff + mstep);

#pragma unroll
            for (int mt = 0; mt < 2; ++mt) {
                const uint32_t* aP = mt ? a1 : a0;
#pragma unroll
                for (int nt = 0; nt < 4; ++nt) {
                    const uint32_t* bP = (nt < 2) ? b0 : b1;
                    int p = (nt & 1) * 2;
                    mma_f32(acc[mt][nt], aP, bP[p], bP[p + 1]);
                }
            }
        }
        __syncthreads();
    }

#pragma unroll
    for (int mt = 0; mt < 2; ++mt) {
#pragma unroll
        for (int nt = 0; nt < 4; ++nt) {
            int r0 = bm + wm + mt * 16 + (lane >> 2);
            int cg = bn + wn + nt * 8 + ((lane & 3) << 1);
            float b0 = bias[cg], b1 = bias[cg + 1];
            *(__half2*)(C + (size_t)r0 * Nc + cg) =
                __floats2half2_rn(acc[mt][nt][0] + b0, acc[mt][nt][1] + b1);
            *(__half2*)(C + (size_t)(r0 + 8) * Nc + cg) =
                __floats2half2_rn(acc[mt][nt][2] + b0, acc[mt][nt][3] + b1);
        }
    }
}

// ===========================================================================
// Persistent fused GRU scan. Grid (16, 8) = 128 CTAs x 256 threads.
// h written ONCE per step, fp16, into hist[t] (LN reads it later).
// W_hh slice resident in smem; full-K h staging; per-envgroup barriers.
// ===========================================================================
#define WSTR 520
#define HSTR 520
#define SM_W  0
#define SM_H  (96 * WSTR)
#define SMEM_ELEMS (96 * WSTR + 64 * HSTR)   // 162.5 KB

__global__ void __launch_bounds__(256)
gru_scan(const __half* __restrict__ gi_all, const float* __restrict__ masks,
         const __half* __restrict__ h0init, const float* __restrict__ b_hh,
         float* __restrict__ out, __half* __restrict__ hist)
{
    extern __shared__ __half sm[];
    __half* sW = sm + SM_W;
    __half* sH = sm + SM_H;

    const int tid  = threadIdx.x;
    const int w    = tid >> 5;
    const int lane = tid & 31;
    const int wq   = w >> 1;
    const int wr   = w & 1;
    const int c0   = blockIdx.x * 32;
    const int gy   = blockIdx.y;
    const int bm   = gy * 64;

    const uint32_t sWB = (uint32_t)__cvta_generic_to_shared(sW);
    const uint32_t sHB = (uint32_t)__cvta_generic_to_shared(sH);

    // ---- stage W_hh slice once: 96 rows x 512 K ----
    for (int i = tid; i < 96 * 64; i += 256) {
        int row = i >> 6;
        int seg = (i & 63) << 3;
        int ch  = row >> 5;
        int c   = row & 31;
        size_t g = (size_t)(ch * HID + c0 + c) * HID + seg;
        *(uint4*)&sW[row * WSTR + seg] = *(const uint4*)&g_whh[g];
    }

    const int env0 = bm + wq * 16 + (lane >> 2);
    const int env1 = env0 + 8;
    const int colbase = c0 + wr * 16;

    float bh[3][2][2], hprev[2][2][2];
#pragma unroll
    for (int ch = 0; ch < 3; ++ch)
#pragma unroll
        for (int nt = 0; nt < 2; ++nt) {
            int col = colbase + nt * 8 + ((lane & 3) << 1);
            bh[ch][nt][0] = b_hh[ch * HID + col];
            bh[ch][nt][1] = b_hh[ch * HID + col + 1];
        }
#pragma unroll
    for (int e = 0; e < 2; ++e)
#pragma unroll
        for (int nt = 0; nt < 2; ++nt) {
            int env = e ? env1 : env0;
            int col = colbase + nt * 8 + ((lane & 3) << 1);
            float2 v = __half22float2(*(const __half2*)&h0init[(size_t)env * HID + col]);
            hprev[e][nt][0] = v.x; hprev[e][nt][1] = v.y;
        }

    const int a_row = wq * 16 + (lane & 7) + (((lane >> 3) & 1) << 3);
    const int a_k   = (lane >> 4) << 3;
    const int b_rowL = wr * 16 + (lane & 7) + ((lane >> 4) << 3);
    const int b_k   = ((lane >> 3) & 1) << 3;

    __syncthreads();

    for (int t = 0; t < T_STEPS; ++t) {
        const __half* Rd = (t == 0) ? h0init
                                    : (hist + (size_t)(t - 1) * N_ENV * HID);
        __half* Hw = hist + (size_t)t * N_ENV * HID;
        const float* mrow = masks + (size_t)t * N_ENV;

        float m_e0 = mrow[env0];
        float m_e1 = mrow[env1];

        // ---- prefetch gate inputs (fp16, DRAM) early ----
        float grv[2][2][2], gzv[2][2][2], gnv[2][2][2];
        {
            const __half* gip = gi_all + (size_t)t * N_ENV * G3;
#pragma unroll
            for (int e = 0; e < 2; ++e) {
                int env = e ? env1 : env0;
#pragma unroll
                for (int nt = 0; nt < 2; ++nt) {
                    int col = colbase + nt * 8 + ((lane & 3) << 1);
                    size_t gb = (size_t)env * G3 + col;
                    float2 a = __half22float2(*(const __half2*)&gip[gb]);
                    float2 b = __half22float2(*(const __half2*)&gip[gb + HID]);
                    float2 c = __half22float2(*(const __half2*)&gip[gb + 2 * HID]);
                    grv[e][nt][0] = a.x; grv[e][nt][1] = a.y;
                    gzv[e][nt][0] = b.x; gzv[e][nt][1] = b.y;
                    gnv[e][nt][0] = c.x; gnv[e][nt][1] = c.y;
                }
            }
        }

        // ---- stage full h tile (64 envs x 512 K), mask-zero dead rows ----
#pragma unroll 4
        for (int i = tid; i < 64 * 64; i += 256) {
            int row = i >> 6;
            int seg = (i & 63) << 3;
            float m = mrow[bm + row];
            uint4 v = *(const uint4*)&Rd[(size_t)(bm + row) * HID + seg];
            if (m == 0.0f) v = make_uint4(0, 0, 0, 0);
            *(uint4*)&sH[row * HSTR + seg] = v;
        }
        __syncthreads();

        float acc[3][2][4];
#pragma unroll
        for (int ch = 0; ch < 3; ++ch)
#pragma unroll
            for (int nt = 0; nt < 2; ++nt)
#pragma unroll
                for (int j = 0; j < 4; ++j) acc[ch][nt][j] = 0.0f;

#pragma unroll 8
        for (int kk = 0; kk < 512; kk += 16) {
            uint32_t aoff = (uint32_t)((a_row * HSTR + kk + a_k) * 2);
            uint32_t ah[4];
            ldsm_x4(ah[0], ah[1], ah[2], ah[3], sHB + aoff);

#pragma unroll
            for (int ch = 0; ch < 3; ++ch) {
                uint32_t boff = (uint32_t)(((ch * 32 + b_rowL) * WSTR
                                           + kk + b_k) * 2);
                uint32_t bk[4];
                ldsm_x4(bk[0], bk[1], bk[2], bk[3], sWB + boff);
#pragma unroll
                for (int nt = 0; nt < 2; ++nt) {
                    int p = nt * 2;
                    mma_f32(acc[ch][nt], ah, bk[p], bk[p + 1]);
                }
            }
        }

        // ---- fused gate; single fp16 hist store per element ----
#pragma unroll
        for (int e = 0; e < 2; ++e) {
            int env = e ? env1 : env0;
            float m = e ? m_e1 : m_e0;
#pragma unroll
            for (int nt = 0; nt < 2; ++nt) {
                int col = colbase + nt * 8 + ((lane & 3) << 1);
                int j0 = 2 * e;

                float hr0 = acc[0][nt][j0]     + bh[0][nt][0];
                float hr1 = acc[0][nt][j0 + 1] + bh[0][nt][1];
                float hz0 = acc[1][nt][j0]     + bh[1][nt][0];
                float hz1 = acc[1][nt][j0 + 1] + bh[1][nt][1];
                float hn0 = acc[2][nt][j0]     + bh[2][nt][0];
                float hn1 = acc[2][nt][j0 + 1] + bh[2][nt][1];

                float r0 = fast_sigmoid(grv[e][nt][0] + hr0);
                float r1 = fast_sigmoid(grv[e][nt][1] + hr1);
                float z0 = fast_sigmoid(gzv[e][nt][0] + hz0);
                float z1 = fast_sigmoid(gzv[e][nt][1] + hz1);
                float n0 = fast_tanh(gnv[e][nt][0] + r0 * hn0);
                float n1 = fast_tanh(gnv[e][nt][1] + r1 * hn1);

                float h0v = hprev[e][nt][0] * m;
                float h1v = hprev[e][nt][1] * m;
                float hw0 = (1.0f - z0) * n0 + z0 * h0v;
                float hw1 = (1.0f - z1) * n1 + z1 * h1v;
                hprev[e][nt][0] = hw0;
                hprev[e][nt][1] = hw1;

                *(__half2*)&Hw[(size_t)env * HID + col]
                    = __floats2half2_rn(hw0, hw1);
                if (t == T_STEPS - 1) {
                    *(float2*)&out[(size_t)T_STEPS * N_ENV * HID
                                   + (size_t)env * HID + col]
                        = make_float2(hw0, hw1);
                }
            }
        }

        // ---- per-envgroup barrier (16 CTAs sharing gy) ----
        if (t < T_STEPS - 1) {
            __threadfence();
            __syncthreads();
            if (tid == 0) {
                atomicAdd(&g_bar8[gy], 1u);
                unsigned target = 16u * (unsigned)(t + 1);
                while (*(volatile unsigned*)&g_bar8[gy] < target) { }
            }
            __syncthreads();
            __threadfence();
        }
    }
}

// ---------------------------------------------------------------------------
// LayerNorm: reads fp16 hist rows, writes fp32 normed rows into d_out.
// ---------------------------------------------------------------------------
__global__ void __launch_bounds__(128)
layernorm_rows(const __half* __restrict__ hist, float* __restrict__ out,
               const float* __restrict__ w, const float* __restrict__ b)
{
    __shared__ float ss[4], sqs[4];
    const __half* p = hist + (size_t)blockIdx.x * HID;
    float* q = out + (size_t)blockIdx.x * HID;
    int t = threadIdx.x;

    float2 v01 = __half22float2(((const __half2*)p)[2 * t]);
    float2 v23 = __half22float2(((const __half2*)p)[2 * t + 1]);
    float4 v = make_float4(v01.x, v01.y, v23.x, v23.y);

    float s  = v.x + v.y + v.z + v.w;
    float sq = v.x * v.x + v.y * v.y + v.z * v.z + v.w * v.w;

#pragma unroll
    for (int o = 16; o > 0; o >>= 1) {
        s  += __shfl_xor_sync(0xffffffffu, s,  o);
        sq += __shfl_xor_sync(0xffffffffu, sq, o);
    }
    int warp = t >> 5;
    if ((t & 31) == 0) { ss[warp] = s; sqs[warp] = sq; }
    __syncthreads();
    s  = ss[0]  + ss[1]  + ss[2]  + ss[3];
    sq = sqs[0] + sqs[1] + sqs[2] + sqs[3];

    float mu  = s * (1.0f / HID);
    float var = sq * (1.0f / HID) - mu * mu;
    float inv = rsqrtf(var + LN_EPS);

    float4 wv = ((const float4*)w)[t];
    float4 bv = ((const float4*)b)[t];
    float4 o;
    o.x = (v.x - mu) * inv * wv.x + bv.x;
    o.y = (v.y - mu) * inv * wv.y + bv.y;
    o.z = (v.z - mu) * inv * wv.z + bv.z;
    o.w = (v.w - mu) * inv * wv.w + bv.w;
    ((float4*)q)[t] = o;
}

// ---------------------------------------------------------------------------
extern "C" void kernel_launch(void* const* d_in, const int* in_sizes, int n_in,
                              void* d_out, int out_size)
{
    const float* x     = (const float*)d_in[0];
    const float* hxs   = (const float*)d_in[1];
    const float* masks = (const float*)d_in[2];
    const float* W_ih  = (const float*)d_in[3];
    const float* W_hh  = (const float*)d_in[4];
    const float* b_ih  = (const float*)d_in[5];
    const float* b_hh  = (const float*)d_in[6];
    const float* ln_w  = (const float*)d_in[7];
    const float* ln_b  = (const float*)d_in[8];
    float* out = (float*)d_out;

    __half *gi, *xf, *wih, *whh, *h0;
    unsigned* barp;
    cudaGetSymbolAddress((void**)&gi, g_gi);
    cudaGetSymbolAddress((void**)&xf, g_xf);
    cudaGetSymbolAddress((void**)&wih, g_wih);
    cudaGetSymbolAddress((void**)&whh, g_whh);
    cudaGetSymbolAddress((void**)&h0, g_h0);
    cudaGetSymbolAddress((void**)&barp, g_bar8);

    cudaMemsetAsync(barp, 0, 8 * sizeof(unsigned));

    // 0) One-time fp32 -> fp16 conversions.
    {
        int n4;
        n4 = T_STEPS * N_ENV * IN_D / 4;
        cvt_fp16<<<(n4 + 255) / 256, 256>>>(x, xf, n4);
        n4 = G3 * IN_D / 4;
        cvt_fp16<<<(n4 + 255) / 256, 256>>>(W_ih, wih, n4);
        n4 = G3 * HID / 4;
        cvt_fp16<<<(n4 + 255) / 256, 256>>>(W_hh, whh, n4);
        n4 = N_ENV * HID / 4;
        cvt_fp16<<<(n4 + 255) / 256, 256>>>(hxs, h0, n4);
    }

    // 1) GI = x @ W_ih^T + b_ih (fp16 out). Consumes xf completely.
    {
        dim3 grid(G3 / 64, (T_STEPS * N_ENV) / 128);
        gemm_gi<<<grid, 256>>>(xf, wih, b_ih, gi, G3, IN_D);
    }

    // 2) Persistent fused scan; writes hist into xf (now dead) + h_last tail.
    {
        size_t smem = (size_t)SMEM_ELEMS * sizeof(__half);
        cudaFuncSetAttribute(gru_scan, cudaFuncAttributeMaxDynamicSharedMemorySize,
                             (int)smem);
        dim3 grid(HID / 32, N_ENV / 64);   // 16 x 8 = 128 CTAs
        gru_scan<<<grid, 256, smem>>>(gi, masks, h0, b_hh, out, xf);
    }

    // 3) LayerNorm: fp16 hist -> fp32 normed out.
    layernorm_rows<<<T_STEPS * N_ENV, 128>>>(xf, out, ln_w, ln_b);
}